// round 9
// baseline (speedup 1.0000x reference)
#include <cuda_runtime.h>
#include <cuda_fp16.h>
#include <math.h>
#include <stdint.h>

// ---------------- problem constants ----------------
#define Lq     2048
#define HIDm   4096
#define Hh     128
#define Pp     64
#define Nn     128
#define Gg     8
#define Kk     4
#define CSz    256
#define NC     8            // L / CS
#define INTERC 8192         // H*P
#define CONVC  10240        // INTER + 2*G*N
#define PROJC  18560        // INTER + CONV + H
#define GSZ    1024         // INTER / G
#define EPSf   1e-5f

// ---------------- scratch (static device globals; no allocation) ----------------
__device__ float d_proj[(size_t)Lq * PROJC];
__device__ float d_xbc [(size_t)Lq * CONVC];
__device__ float d_dt  [(size_t)Lq * Hh];
__device__ float d_cum [(size_t)Lq * Hh];
__device__ float d_y   [(size_t)Lq * INTERC];
__device__ float d_st  [(size_t)NC * Hh * Pp * Nn];
__device__ float d_prev[(size_t)NC * Hh * Pp * Nn];
// fp16 GEMM operands
__device__ __align__(16) __half d_ha [(size_t)Lq * HIDm];
__device__ __align__(16) __half d_hb1[(size_t)PROJC * HIDm];
__device__ __align__(16) __half d_hb2[(size_t)HIDm * INTERC];
__device__ __align__(16) __half d_gh [(size_t)Lq * INTERC];

__device__ __forceinline__ uint32_t smem_u32(const void* p) {
    return (uint32_t)__cvta_generic_to_shared(p);
}
__device__ __forceinline__ void cp16(uint32_t dst, const void* src) {
    asm volatile("cp.async.cg.shared.global [%0], [%1], 16;\n" :: "r"(dst), "l"(src));
}
__device__ __forceinline__ void mma_f16(float* c, const uint32_t* a, const uint32_t* b) {
    asm volatile(
        "mma.sync.aligned.m16n8k16.row.col.f32.f16.f16.f32 "
        "{%0,%1,%2,%3}, {%4,%5,%6,%7}, {%8,%9}, {%0,%1,%2,%3};"
        : "+f"(c[0]), "+f"(c[1]), "+f"(c[2]), "+f"(c[3])
        : "r"(a[0]), "r"(a[1]), "r"(a[2]), "r"(a[3]), "r"(b[0]), "r"(b[1]));
}
__device__ __forceinline__ void ldm_x4(uint32_t* r, uint32_t addr) {
    asm volatile("ldmatrix.sync.aligned.m8n8.x4.shared.b16 {%0,%1,%2,%3}, [%4];"
                 : "=r"(r[0]), "=r"(r[1]), "=r"(r[2]), "=r"(r[3]) : "r"(addr));
}

// ---------------- fp32 -> fp16 pre-convert ----------------
__global__ void __launch_bounds__(256)
cvt_f16_k(const float4* __restrict__ in, uint2* __restrict__ outp, int n4) {
    int i = blockIdx.x * 256 + threadIdx.x;
    if (i >= n4) return;
    float4 v = in[i];
    __half2 lo = __floats2half2_rn(v.x, v.y);
    __half2 hi = __floats2half2_rn(v.z, v.w);
    uint2 o;
    o.x = *(const uint32_t*)&lo;
    o.y = *(const uint32_t*)&hi;
    outp[i] = o;
}

// =====================================================================
//  fp16 mma GEMM: C[M,Ncols] = A[M,K] @ B[Ncols,K]^T (half in, f32 out)
//  CTA tile 128x128, BK=64, 128 thr, 4 warps (2m x 2n, 64x64 each),
//  3-stage ring, ldmatrix, 2 CTAs/SM. smem traffic 96 B/cyc at peak.
// =====================================================================
#define BMt 128
#define BNt 128
#define BKh 64                          // K per chunk (halves)
#define PADh 72                         // halves per smem row (144 B)
#define STAGE_H ((BMt + BNt) * PADh)    // 18432 halves = 36864 B
#define GM_SMEM (3 * STAGE_H * 2)       // 110592 bytes

__device__ __forceinline__ void gemm_f16_body(const __half* __restrict__ A,
                                              const __half* __restrict__ B,
                                              float* __restrict__ C,
                                              int Ncols, int K) {
    extern __shared__ __half smh[];
    const uint32_t sbase = smem_u32(smh);
    const int tid = threadIdx.x, wid = tid >> 5, lane = tid & 31;
    const int g = lane >> 2, q = lane & 3;
    const int m0 = blockIdx.x * BMt;
    const int n0 = blockIdx.y * BNt;
    const int wm = (wid >> 1) * 64;          // 2 m-warps x 64 rows
    const int wn = (wid & 1) * 64;           // 2 n-warps x 64 cols
    const int nk = K / BKh;

    // ldmatrix per-thread address offsets (bytes within stage)
    const int a_row = wm + (lane & 15);
    const int a_kh  = ((lane >> 4) & 1) * 8;
    const uint32_t a_off = (uint32_t)(a_row * PADh + a_kh) * 2;
    const int b_nrow = (lane & 7) + ((lane >> 4) & 1) * 8;
    const int b_kh   = ((lane >> 3) & 1) * 8;
    const uint32_t b_off = (uint32_t)(BMt * PADh + (wn + b_nrow) * PADh + b_kh) * 2;

    float acc[4][8][4];                      // 4 m16-tiles x 8 n8-tiles
#pragma unroll
    for (int i = 0; i < 4; ++i)
#pragma unroll
        for (int j = 0; j < 8; ++j)
#pragma unroll
            for (int r = 0; r < 4; ++r) acc[i][j][r] = 0.f;

    auto load_stage = [&](int c) {
        const int s = c % 3;
        const int k0 = c * BKh;
        const uint32_t abase = sbase + s * STAGE_H * 2;
        const uint32_t bbase = abase + BMt * PADh * 2;
#pragma unroll
        for (int i = 0; i < 8; ++i) {        // A: 128 rows x 8 cp16
            int t = tid + i * 128;
            int r = t >> 3, qq = t & 7;
            cp16(abase + (uint32_t)(r * PADh + qq * 8) * 2,
                 A + (size_t)(m0 + r) * K + k0 + qq * 8);
        }
#pragma unroll
        for (int i = 0; i < 8; ++i) {        // B: 128 rows x 8 cp16
            int t = tid + i * 128;
            int r = t >> 3, qq = t & 7;
            cp16(bbase + (uint32_t)(r * PADh + qq * 8) * 2,
                 B + (size_t)(n0 + r) * K + k0 + qq * 8);
        }
        asm volatile("cp.async.commit_group;");
    };

    load_stage(0);
    load_stage(1);

    for (int c = 0; c < nk; ++c) {
        if (c + 1 < nk) {
            asm volatile("cp.async.wait_group 1;");
        } else {
            asm volatile("cp.async.wait_group 0;");
        }
        __syncthreads();

        if (c + 2 < nk) load_stage(c + 2);

        const uint32_t stg = sbase + (uint32_t)(c % 3) * STAGE_H * 2;
        const uint32_t a_addr = stg + a_off;
        const uint32_t b_addr = stg + b_off;

#pragma unroll
        for (int ks = 0; ks < 4; ++ks) {
            const uint32_t kadd = (uint32_t)ks * 32;   // 16 halves
            uint32_t af[4][4];
#pragma unroll
            for (int mb = 0; mb < 4; ++mb)
                ldm_x4(af[mb], a_addr + (uint32_t)(mb * 16 * PADh) * 2 + kadd);
            uint32_t bf[4][4];
#pragma unroll
            for (int nb = 0; nb < 4; ++nb)
                ldm_x4(bf[nb], b_addr + (uint32_t)(nb * 16 * PADh) * 2 + kadd);
#pragma unroll
            for (int mi = 0; mi < 4; ++mi)
#pragma unroll
                for (int ni = 0; ni < 8; ++ni)
                    mma_f16(acc[mi][ni], af[mi], &bf[ni >> 1][(ni & 1) * 2]);
        }
    }

#pragma unroll
    for (int mi = 0; mi < 4; ++mi) {
        const int r = m0 + wm + mi * 16 + g;
#pragma unroll
        for (int ni = 0; ni < 8; ++ni) {
            const int cb = n0 + wn + ni * 8 + 2 * q;
            *(float2*)(C + (size_t)r * Ncols + cb) =
                make_float2(acc[mi][ni][0], acc[mi][ni][1]);
            *(float2*)(C + (size_t)(r + 8) * Ncols + cb) =
                make_float2(acc[mi][ni][2], acc[mi][ni][3]);
        }
    }
}

__global__ void __launch_bounds__(128, 2)
gemm1_mma_k() { gemm_f16_body(d_ha, d_hb1, d_proj, PROJC, HIDm); }
__global__ void __launch_bounds__(128, 2)
gemm2_mma_k(float* __restrict__ C) { gemm_f16_body(d_gh, d_hb2, C, HIDm, INTERC); }

// ---------------- depthwise causal conv (K=4) + SiLU ----------------
__global__ void __launch_bounds__(256)
conv_silu_k(const float* __restrict__ w, const float* __restrict__ b) {
    int c = blockIdx.x * 256 + threadIdx.x;
    int l = blockIdx.y;
    if (c >= CONVC) return;
    float acc = b[c];
#pragma unroll
    for (int k = 0; k < Kk; ++k) {
        int ls = l - (Kk - 1) + k;
        if (ls >= 0) acc += w[c * Kk + k] * d_proj[(size_t)ls * PROJC + INTERC + c];
    }
    d_xbc[(size_t)l * CONVC + c] = acc / (1.f + __expf(-acc));
}

// ---------------- dt softplus + per-chunk cumsum of dA ----------------
__global__ void __launch_bounds__(256)
dt_cum_k(const float* __restrict__ dt_bias, const float* __restrict__ A_log) {
    int h = blockIdx.x, c = blockIdx.y, t = threadIdx.x;
    int l = c * CSz + t;
    float x = d_proj[(size_t)l * PROJC + (INTERC + CONVC) + h] + dt_bias[h];
    float sp = fmaxf(x, 0.f) + log1pf(expf(-fabsf(x)));
    float dtv = fmaxf(sp, 0.f);
    float A = -expf(A_log[h]);
    __shared__ float s[CSz];
    s[t] = dtv * A;
    __syncthreads();
    for (int off = 1; off < CSz; off <<= 1) {
        float v = (t >= off) ? s[t - off] : 0.f;
        __syncthreads();
        s[t] += v;
        __syncthreads();
    }
    d_dt [(size_t)l * Hh + h] = dtv;
    d_cum[(size_t)l * Hh + h] = s[t];
}

// ---------------- intra-chunk: y_intra = (CB^T * Ldec * dt) @ x ----------------
#define IT_SMEM ((2 * 128 * 68 + 2 * 64 * 68 + 192) * 4)
__global__ void __launch_bounds__(256, 2)
ssd_intra_k() {
    extern __shared__ float sdyn[];
    float* CsT = sdyn;                 // [n][i]  128x68
    float* BsT = CsT + 128 * 68;       // [n][j]  128x68
    float* SsT = BsT + 128 * 68;       // [j][i]   64x68
    float* Xs  = SsT + 64 * 68;        // [j][p]   64x68
    float* cum_i = Xs + 64 * 68;
    float* cum_j = cum_i + 64;
    float* dtj   = cum_j + 64;

    const int it = blockIdx.x, h = blockIdx.y, c = blockIdx.z;
    const int g = h >> 4;
    const int tid = threadIdx.x;
    const int tx = tid & 15, ty = tid >> 4;

    const int li0 = c * CSz + it * 64;
    const int ccol = INTERC + Gg * Nn + g * Nn;
    const int bcol = INTERC + g * Nn;

#pragma unroll
    for (int rep = 0; rep < 2; ++rep) {
        int b = tid + rep * 256;
        int bi = (b & 15) * 4;
        int bn = (b >> 4) * 4;
        float4 r0 = *(const float4*)(&d_xbc[(size_t)(li0 + bi + 0) * CONVC + ccol + bn]);
        float4 r1 = *(const float4*)(&d_xbc[(size_t)(li0 + bi + 1) * CONVC + ccol + bn]);
        float4 r2 = *(const float4*)(&d_xbc[(size_t)(li0 + bi + 2) * CONVC + ccol + bn]);
        float4 r3 = *(const float4*)(&d_xbc[(size_t)(li0 + bi + 3) * CONVC + ccol + bn]);
        *(float4*)&CsT[(bn + 0) * 68 + bi] = make_float4(r0.x, r1.x, r2.x, r3.x);
        *(float4*)&CsT[(bn + 1) * 68 + bi] = make_float4(r0.y, r1.y, r2.y, r3.y);
        *(float4*)&CsT[(bn + 2) * 68 + bi] = make_float4(r0.z, r1.z, r2.z, r3.z);
        *(float4*)&CsT[(bn + 3) * 68 + bi] = make_float4(r0.w, r1.w, r2.w, r3.w);
    }
    if (tid < 64) cum_i[tid] = d_cum[(size_t)(li0 + tid) * Hh + h];

    float yacc[4][4];
#pragma unroll
    for (int i = 0; i < 4; ++i)
#pragma unroll
        for (int j = 0; j < 4; ++j) yacc[i][j] = 0.f;

    for (int jt = 0; jt <= it; ++jt) {
        const int lj0 = c * CSz + jt * 64;
        __syncthreads();
#pragma unroll
        for (int rep = 0; rep < 2; ++rep) {
            int b = tid + rep * 256;
            int bi = (b & 15) * 4;
            int bn = (b >> 4) * 4;
            float4 r0 = *(const float4*)(&d_xbc[(size_t)(lj0 + bi + 0) * CONVC + bcol + bn]);
            float4 r1 = *(const float4*)(&d_xbc[(size_t)(lj0 + bi + 1) * CONVC + bcol + bn]);
            float4 r2 = *(const float4*)(&d_xbc[(size_t)(lj0 + bi + 2) * CONVC + bcol + bn]);
            float4 r3 = *(const float4*)(&d_xbc[(size_t)(lj0 + bi + 3) * CONVC + bcol + bn]);
            *(float4*)&BsT[(bn + 0) * 68 + bi] = make_float4(r0.x, r1.x, r2.x, r3.x);
            *(float4*)&BsT[(bn + 1) * 68 + bi] = make_float4(r0.y, r1.y, r2.y, r3.y);
            *(float4*)&BsT[(bn + 2) * 68 + bi] = make_float4(r0.z, r1.z, r2.z, r3.z);
            *(float4*)&BsT[(bn + 3) * 68 + bi] = make_float4(r0.w, r1.w, r2.w, r3.w);
        }
#pragma unroll
        for (int rep = 0; rep < 4; ++rep) {
            int idx = tid + rep * 256;
            int r = idx >> 4, qq = idx & 15;
            *(float4*)&Xs[r * 68 + qq * 4] =
                *(const float4*)(&d_xbc[(size_t)(lj0 + r) * CONVC + h * Pp + qq * 4]);
        }
        if (tid < 64) {
            cum_j[tid] = d_cum[(size_t)(lj0 + tid) * Hh + h];
            dtj  [tid] = d_dt [(size_t)(lj0 + tid) * Hh + h];
        }
        __syncthreads();

        float sacc[4][4];
#pragma unroll
        for (int i = 0; i < 4; ++i)
#pragma unroll
            for (int j = 0; j < 4; ++j) sacc[i][j] = 0.f;
#pragma unroll 8
        for (int kk = 0; kk < 128; ++kk) {
            float4 a4 = *(const float4*)&CsT[kk * 68 + ty * 4];
            float4 b4 = *(const float4*)&BsT[kk * 68 + tx * 4];
            float a[4] = {a4.x, a4.y, a4.z, a4.w};
            float b[4] = {b4.x, b4.y, b4.z, b4.w};
#pragma unroll
            for (int i = 0; i < 4; ++i)
#pragma unroll
                for (int j = 0; j < 4; ++j) sacc[i][j] += a[i] * b[j];
        }
#pragma unroll
        for (int jj = 0; jj < 4; ++jj) {
            int gj = jt * 64 + tx * 4 + jj;
            float cjv = cum_j[tx * 4 + jj];
            float djv = dtj[tx * 4 + jj];
            float v[4];
#pragma unroll
            for (int ii = 0; ii < 4; ++ii) {
                int gi = it * 64 + ty * 4 + ii;
                v[ii] = (gi >= gj) ? sacc[ii][jj] * __expf(cum_i[ty * 4 + ii] - cjv) * djv : 0.f;
            }
            *(float4*)&SsT[(tx * 4 + jj) * 68 + ty * 4] = make_float4(v[0], v[1], v[2], v[3]);
        }
        __syncthreads();

#pragma unroll 8
        for (int kkj = 0; kkj < 64; ++kkj) {
            float4 a4 = *(const float4*)&SsT[kkj * 68 + ty * 4];
            float4 b4 = *(const float4*)&Xs[kkj * 68 + tx * 4];
            float a[4] = {a4.x, a4.y, a4.z, a4.w};
            float b[4] = {b4.x, b4.y, b4.z, b4.w};
#pragma unroll
            for (int i = 0; i < 4; ++i)
#pragma unroll
                for (int j = 0; j < 4; ++j) yacc[i][j] += a[i] * b[j];
        }
    }
#pragma unroll
    for (int i = 0; i < 4; ++i) {
        *(float4*)(&d_y[(size_t)(li0 + ty * 4 + i) * INTERC + h * Pp + tx * 4]) =
            make_float4(yacc[i][0], yacc[i][1], yacc[i][2], yacc[i][3]);
    }
}

// ---------------- chunk states ----------------
__global__ void __launch_bounds__(256)
ssd_states_k() {
    const int h = blockIdx.x, c = blockIdx.y;
    const int g = h >> 4;
    const int tid = threadIdx.x;
    const int tx = tid & 15, ty = tid >> 4;

    __shared__ float Xs[32][68];
    __shared__ float Bsh[32][132];
    __shared__ float ws[32];

    float acc[4][8];
#pragma unroll
    for (int i = 0; i < 4; ++i)
#pragma unroll
        for (int j = 0; j < 8; ++j) acc[i][j] = 0.f;

    const float cum_last = d_cum[(size_t)(c * CSz + CSz - 1) * Hh + h];

    for (int j0 = 0; j0 < CSz; j0 += 32) {
        __syncthreads();
#pragma unroll
        for (int rep = 0; rep < 2; ++rep) {
            int idx = tid + rep * 256;
            int r = idx >> 4, q = idx & 15;
            *(float4*)&Xs[r][q * 4] =
                *(const float4*)(&d_xbc[(size_t)(c * CSz + j0 + r) * CONVC + h * Pp + q * 4]);
        }
#pragma unroll
        for (int rep = 0; rep < 4; ++rep) {
            int idx = tid + rep * 256;
            int r = idx >> 5, q = idx & 31;
            *(float4*)&Bsh[r][q * 4] =
                *(const float4*)(&d_xbc[(size_t)(c * CSz + j0 + r) * CONVC + INTERC + g * Nn + q * 4]);
        }
        if (tid < 32) {
            int l = c * CSz + j0 + tid;
            ws[tid] = d_dt[(size_t)l * Hh + h] * __expf(cum_last - d_cum[(size_t)l * Hh + h]);
        }
        __syncthreads();
#pragma unroll 4
        for (int j = 0; j < 32; ++j) {
            float w = ws[j];
            float4 a4 = *(const float4*)&Xs[j][ty * 4];
            float aw[4] = {a4.x * w, a4.y * w, a4.z * w, a4.w * w};
            float4 b0 = *(const float4*)&Bsh[j][tx * 8];
            float4 b1 = *(const float4*)&Bsh[j][tx * 8 + 4];
            float b[8] = {b0.x, b0.y, b0.z, b0.w, b1.x, b1.y, b1.z, b1.w};
#pragma unroll
            for (int i = 0; i < 4; ++i)
#pragma unroll
                for (int jn = 0; jn < 8; ++jn) acc[i][jn] += aw[i] * b[jn];
        }
    }
#pragma unroll
    for (int i = 0; i < 4; ++i) {
        size_t base = ((size_t)(c * Hh + h) * Pp + ty * 4 + i) * Nn + tx * 8;
        *(float4*)&d_st[base]     = make_float4(acc[i][0], acc[i][1], acc[i][2], acc[i][3]);
        *(float4*)&d_st[base + 4] = make_float4(acc[i][4], acc[i][5], acc[i][6], acc[i][7]);
    }
}

// ---------------- inter-chunk scan ----------------
__global__ void __launch_bounds__(256)
ssd_scan_k() {
    int idx = blockIdx.x * 256 + threadIdx.x;
    if (idx >= Hh * Pp * Nn) return;
    int h = idx / (Pp * Nn);
    float carry = 0.f;
#pragma unroll
    for (int c = 0; c < NC; ++c) {
        d_prev[(size_t)c * Hh * Pp * Nn + idx] = carry;
        float cdec = __expf(d_cum[(size_t)(c * CSz + CSz - 1) * Hh + h]);
        carry = cdec * carry + d_st[(size_t)c * Hh * Pp * Nn + idx];
    }
}

// ---------------- inter-chunk output + D*x ----------------
__global__ void __launch_bounds__(256)
ssd_inter_k(const float* __restrict__ Dp) {
    const int it = blockIdx.x, h = blockIdx.y, c = blockIdx.z;
    const int g = h >> 4;
    const int tid = threadIdx.x;
    const int tx = tid & 15, ty = tid >> 4;

    __shared__ float CsT[64 * 68];
    __shared__ float Pn [64 * 68];

    const int li0 = c * CSz + it * 64;
    const int ccol = INTERC + Gg * Nn + g * Nn;
    const size_t pbase = ((size_t)(c * Hh + h) * Pp) * Nn;

    float acc[4][4];
#pragma unroll
    for (int i = 0; i < 4; ++i)
#pragma unroll
        for (int j = 0; j < 4; ++j) acc[i][j] = 0.f;

#pragma unroll
    for (int nt = 0; nt < 2; ++nt) {
        __syncthreads();
        {
            int bi = (tid & 15) * 4;
            int bn = (tid >> 4) * 4;
            float4 r0 = *(const float4*)(&d_xbc[(size_t)(li0 + bi + 0) * CONVC + ccol + nt * 64 + bn]);
            float4 r1 = *(const float4*)(&d_xbc[(size_t)(li0 + bi + 1) * CONVC + ccol + nt * 64 + bn]);
            float4 r2 = *(const float4*)(&d_xbc[(size_t)(li0 + bi + 2) * CONVC + ccol + nt * 64 + bn]);
            float4 r3 = *(const float4*)(&d_xbc[(size_t)(li0 + bi + 3) * CONVC + ccol + nt * 64 + bn]);
            *(float4*)&CsT[(bn + 0) * 68 + bi] = make_float4(r0.x, r1.x, r2.x, r3.x);
            *(float4*)&CsT[(bn + 1) * 68 + bi] = make_float4(r0.y, r1.y, r2.y, r3.y);
            *(float4*)&CsT[(bn + 2) * 68 + bi] = make_float4(r0.z, r1.z, r2.z, r3.z);
            *(float4*)&CsT[(bn + 3) * 68 + bi] = make_float4(r0.w, r1.w, r2.w, r3.w);
            float4 p0 = *(const float4*)(&d_prev[pbase + (size_t)(bi + 0) * Nn + nt * 64 + bn]);
            float4 p1 = *(const float4*)(&d_prev[pbase + (size_t)(bi + 1) * Nn + nt * 64 + bn]);
            float4 p2 = *(const float4*)(&d_prev[pbase + (size_t)(bi + 2) * Nn + nt * 64 + bn]);
            float4 p3 = *(const float4*)(&d_prev[pbase + (size_t)(bi + 3) * Nn + nt * 64 + bn]);
            *(float4*)&Pn[(bn + 0) * 68 + bi] = make_float4(p0.x, p1.x, p2.x, p3.x);
            *(float4*)&Pn[(bn + 1) * 68 + bi] = make_float4(p0.y, p1.y, p2.y, p3.y);
            *(float4*)&Pn[(bn + 2) * 68 + bi] = make_float4(p0.z, p1.z, p2.z, p3.z);
            *(float4*)&Pn[(bn + 3) * 68 + bi] = make_float4(p0.w, p1.w, p2.w, p3.w);
        }
        __syncthreads();
#pragma unroll 8
        for (int kk = 0; kk < 64; ++kk) {
            float4 a4 = *(const float4*)&CsT[kk * 68 + ty * 4];
            float4 b4 = *(const float4*)&Pn[kk * 68 + tx * 4];
            float a[4] = {a4.x, a4.y, a4.z, a4.w};
            float b[4] = {b4.x, b4.y, b4.z, b4.w};
#pragma unroll
            for (int i = 0; i < 4; ++i)
#pragma unroll
                for (int j = 0; j < 4; ++j) acc[i][j] += a[i] * b[j];
        }
    }
    const float Dh = Dp[h];
#pragma unroll
    for (int i = 0; i < 4; ++i) {
        int l = li0 + ty * 4 + i;
        float esc = __expf(d_cum[(size_t)l * Hh + h]);
        size_t yi = (size_t)l * INTERC + h * Pp + tx * 4;
        size_t xi = (size_t)l * CONVC + h * Pp + tx * 4;
        float4 yv = *(const float4*)&d_y[yi];
        float4 xv = *(const float4*)&d_xbc[xi];
        yv.x += esc * acc[i][0] + Dh * xv.x;
        yv.y += esc * acc[i][1] + Dh * xv.y;
        yv.z += esc * acc[i][2] + Dh * xv.z;
        yv.w += esc * acc[i][3] + Dh * xv.w;
        *(float4*)&d_y[yi] = yv;
    }
}

// ---------------- gated RMS group-norm (writes fp16 d_gh) ----------------
__global__ void __launch_bounds__(256)
gated_norm_k(const float* __restrict__ norm_w) {
    const int l = blockIdx.x, grp = blockIdx.y;
    const int tid = threadIdx.x;
    float v[4];
    float ss = 0.f;
#pragma unroll
    for (int i = 0; i < 4; ++i) {
        int col = grp * GSZ + tid + i * 256;
        float gate = d_proj[(size_t)l * PROJC + col];
        float yv = d_y[(size_t)l * INTERC + col];
        float sg = gate / (1.f + __expf(-gate));
        v[i] = yv * sg;
        ss += v[i] * v[i];
    }
#pragma unroll
    for (int off = 16; off; off >>= 1) ss += __shfl_xor_sync(0xffffffffu, ss, off);
    __shared__ float red[8];
    if ((tid & 31) == 0) red[tid >> 5] = ss;
    __syncthreads();
    float tot = red[0] + red[1] + red[2] + red[3] + red[4] + red[5] + red[6] + red[7];
    float rs = rsqrtf(tot / (float)GSZ + EPSf);
#pragma unroll
    for (int i = 0; i < 4; ++i) {
        int col = grp * GSZ + tid + i * 256;
        d_gh[(size_t)l * INTERC + col] = __float2half_rn(v[i] * rs * norm_w[col]);
    }
}

// ---------------- launch ----------------
extern "C" void kernel_launch(void* const* d_in, const int* in_sizes, int n_in,
                              void* d_out, int out_size) {
    const float* input     = (const float*)d_in[0];
    const float* in_proj_w = (const float*)d_in[1];
    const float* conv_w    = (const float*)d_in[2];
    const float* conv_b    = (const float*)d_in[3];
    const float* dt_bias   = (const float*)d_in[4];
    const float* A_log     = (const float*)d_in[5];
    const float* Dp        = (const float*)d_in[6];
    const float* norm_w    = (const float*)d_in[7];
    const float* out_w     = (const float*)d_in[8];
    float* out = (float*)d_out;

    cudaFuncSetAttribute(gemm1_mma_k, cudaFuncAttributeMaxDynamicSharedMemorySize, GM_SMEM);
    cudaFuncSetAttribute(gemm2_mma_k, cudaFuncAttributeMaxDynamicSharedMemorySize, GM_SMEM);
    cudaFuncSetAttribute(ssd_intra_k, cudaFuncAttributeMaxDynamicSharedMemorySize, IT_SMEM);

    __half* ha;  cudaGetSymbolAddress((void**)&ha,  d_ha);
    __half* hb1; cudaGetSymbolAddress((void**)&hb1, d_hb1);
    __half* hb2; cudaGetSymbolAddress((void**)&hb2, d_hb2);

    // 0. fp16 pre-converts
    cvt_f16_k<<<(Lq * HIDm / 4 + 255) / 256, 256>>>((const float4*)input, (uint2*)ha, Lq * HIDm / 4);
    cvt_f16_k<<<(PROJC * HIDm / 4 + 255) / 256, 256>>>((const float4*)in_proj_w, (uint2*)hb1, PROJC * HIDm / 4);
    cvt_f16_k<<<(HIDm * INTERC / 4 + 255) / 256, 256>>>((const float4*)out_w, (uint2*)hb2, HIDm * INTERC / 4);

    // 1. in_proj GEMM (fp16 mma): (2048x4096) @ (18560x4096)^T -> d_proj
    gemm1_mma_k<<<dim3(Lq / BMt, PROJC / BNt), 128, GM_SMEM>>>();
    // 2. depthwise causal conv + SiLU -> d_xbc
    conv_silu_k<<<dim3(CONVC / 256, Lq), 256>>>(conv_w, conv_b);
    // 3. dt softplus + per-chunk cumsum(dA)
    dt_cum_k<<<dim3(Hh, NC), 256>>>(dt_bias, A_log);
    // 4. intra-chunk pass -> d_y
    ssd_intra_k<<<dim3(4, Hh, NC), 256, IT_SMEM>>>();
    // 5. per-chunk states
    ssd_states_k<<<dim3(Hh, NC), 256>>>();
    // 6. inter-chunk sequential scan -> d_prev
    ssd_scan_k<<<(Hh * Pp * Nn) / 256, 256>>>();
    // 7. inter-chunk contribution + D*x -> d_y (final)
    ssd_inter_k<<<dim3(4, Hh, NC), 256>>>(Dp);
    // 8. gated RMS group-norm -> d_gh (fp16)
    gated_norm_k<<<dim3(Lq, Gg), 256>>>(norm_w);
    // 9. out GEMM (fp16 mma): (2048x8192) @ (4096x8192)^T -> out
    gemm2_mma_k<<<dim3(Lq / BMt, HIDm / BNt), 128, GM_SMEM>>>(out);
}

// round 10
// speedup vs baseline: 1.0289x; 1.0289x over previous
#include <cuda_runtime.h>
#include <cuda_fp16.h>
#include <math.h>
#include <stdint.h>

// ---------------- problem constants ----------------
#define Lq     2048
#define HIDm   4096
#define Hh     128
#define Pp     64
#define Nn     128
#define Gg     8
#define Kk     4
#define CSz    256
#define NC     8            // L / CS
#define INTERC 8192         // H*P
#define CONVC  10240        // INTER + 2*G*N
#define PROJC  18560        // INTER + CONV + H
#define GSZ    1024         // INTER / G
#define EPSf   1e-5f

// ---------------- scratch (static device globals; no allocation) ----------------
__device__ float d_proj[(size_t)Lq * PROJC];
__device__ float d_xbc [(size_t)Lq * CONVC];
__device__ float d_dt  [(size_t)Lq * Hh];
__device__ float d_cum [(size_t)Lq * Hh];
__device__ float d_y   [(size_t)Lq * INTERC];
__device__ float d_st  [(size_t)NC * Hh * Pp * Nn];
__device__ float d_prev[(size_t)NC * Hh * Pp * Nn];
// fp16 GEMM operands
__device__ __align__(16) __half d_ha [(size_t)Lq * HIDm];
__device__ __align__(16) __half d_hb1[(size_t)PROJC * HIDm];
__device__ __align__(16) __half d_hb2[(size_t)HIDm * INTERC];
__device__ __align__(16) __half d_gh [(size_t)Lq * INTERC];

__device__ __forceinline__ uint32_t smem_u32(const void* p) {
    return (uint32_t)__cvta_generic_to_shared(p);
}
__device__ __forceinline__ void cp16(uint32_t dst, const void* src) {
    asm volatile("cp.async.cg.shared.global [%0], [%1], 16;\n" :: "r"(dst), "l"(src));
}
__device__ __forceinline__ void mma_f16(float* c, const uint32_t* a, const uint32_t* b) {
    asm volatile(
        "mma.sync.aligned.m16n8k16.row.col.f32.f16.f16.f32 "
        "{%0,%1,%2,%3}, {%4,%5,%6,%7}, {%8,%9}, {%0,%1,%2,%3};"
        : "+f"(c[0]), "+f"(c[1]), "+f"(c[2]), "+f"(c[3])
        : "r"(a[0]), "r"(a[1]), "r"(a[2]), "r"(a[3]), "r"(b[0]), "r"(b[1]));
}
__device__ __forceinline__ void ldm_x4(uint32_t* r, uint32_t addr) {
    asm volatile("ldmatrix.sync.aligned.m8n8.x4.shared.b16 {%0,%1,%2,%3}, [%4];"
                 : "=r"(r[0]), "=r"(r[1]), "=r"(r[2]), "=r"(r[3]) : "r"(addr));
}

// ---------------- fp32 -> fp16 pre-convert ----------------
__global__ void __launch_bounds__(256)
cvt_f16_k(const float4* __restrict__ in, uint2* __restrict__ outp, int n4) {
    int i = blockIdx.x * 256 + threadIdx.x;
    if (i >= n4) return;
    float4 v = in[i];
    __half2 lo = __floats2half2_rn(v.x, v.y);
    __half2 hi = __floats2half2_rn(v.z, v.w);
    uint2 o;
    o.x = *(const uint32_t*)&lo;
    o.y = *(const uint32_t*)&hi;
    outp[i] = o;
}

// =====================================================================
//  fp16 mma GEMM (R7 config): CTA 128x128, BK=64, 256 thr, 8 warps
//  (4m x 2n, 32x64 each), 3-stage ring, ldmatrix, 2 CTAs/SM.
// =====================================================================
#define BMt 128
#define BNt 128
#define BKh 64
#define PADh 72
#define STAGE_H ((BMt + BNt) * PADh)
#define GM_SMEM (3 * STAGE_H * 2)       // 110592 bytes

__device__ __forceinline__ void gemm_f16_body(const __half* __restrict__ A,
                                              const __half* __restrict__ B,
                                              float* __restrict__ C,
                                              int Ncols, int K) {
    extern __shared__ __half smh[];
    const uint32_t sbase = smem_u32(smh);
    const int tid = threadIdx.x, wid = tid >> 5, lane = tid & 31;
    const int g = lane >> 2, q = lane & 3;
    const int m0 = blockIdx.x * BMt;
    const int n0 = blockIdx.y * BNt;
    const int wm = (wid >> 1) * 32;          // 4 m-warps x 32 rows
    const int wn = (wid & 1) * 64;           // 2 n-warps x 64 cols
    const int nk = K / BKh;

    const int a_row = wm + (lane & 15);
    const int a_kh  = ((lane >> 4) & 1) * 8;
    const uint32_t a_off = (uint32_t)(a_row * PADh + a_kh) * 2;
    const int b_nrow = (lane & 7) + ((lane >> 4) & 1) * 8;
    const int b_kh   = ((lane >> 3) & 1) * 8;
    const uint32_t b_off = (uint32_t)(BMt * PADh + (wn + b_nrow) * PADh + b_kh) * 2;

    float acc[2][8][4];
#pragma unroll
    for (int i = 0; i < 2; ++i)
#pragma unroll
        for (int j = 0; j < 8; ++j)
#pragma unroll
            for (int r = 0; r < 4; ++r) acc[i][j][r] = 0.f;

    auto load_stage = [&](int c) {
        const int s = c % 3;
        const int k0 = c * BKh;
        const uint32_t abase = sbase + s * STAGE_H * 2;
        const uint32_t bbase = abase + BMt * PADh * 2;
#pragma unroll
        for (int i = 0; i < 4; ++i) {
            int t = tid + i * 256;
            int r = t >> 3, qq = t & 7;
            cp16(abase + (uint32_t)(r * PADh + qq * 8) * 2,
                 A + (size_t)(m0 + r) * K + k0 + qq * 8);
        }
#pragma unroll
        for (int i = 0; i < 4; ++i) {
            int t = tid + i * 256;
            int r = t >> 3, qq = t & 7;
            cp16(bbase + (uint32_t)(r * PADh + qq * 8) * 2,
                 B + (size_t)(n0 + r) * K + k0 + qq * 8);
        }
        asm volatile("cp.async.commit_group;");
    };

    load_stage(0);
    load_stage(1);

    for (int c = 0; c < nk; ++c) {
        if (c + 1 < nk) {
            asm volatile("cp.async.wait_group 1;");
        } else {
            asm volatile("cp.async.wait_group 0;");
        }
        __syncthreads();

        if (c + 2 < nk) load_stage(c + 2);

        const uint32_t stg = sbase + (uint32_t)(c % 3) * STAGE_H * 2;
        const uint32_t a_addr = stg + a_off;
        const uint32_t b_addr = stg + b_off;

#pragma unroll
        for (int ks = 0; ks < 4; ++ks) {
            const uint32_t kadd = (uint32_t)ks * 32;
            uint32_t af[2][4];
            ldm_x4(af[0], a_addr + kadd);
            ldm_x4(af[1], a_addr + 16 * PADh * 2 + kadd);
            uint32_t bf[4][4];
#pragma unroll
            for (int nb = 0; nb < 4; ++nb)
                ldm_x4(bf[nb], b_addr + (uint32_t)(nb * 16 * PADh) * 2 + kadd);
#pragma unroll
            for (int mi = 0; mi < 2; ++mi)
#pragma unroll
                for (int ni = 0; ni < 8; ++ni)
                    mma_f16(acc[mi][ni], af[mi], &bf[ni >> 1][(ni & 1) * 2]);
        }
    }

#pragma unroll
    for (int mi = 0; mi < 2; ++mi) {
        const int r = m0 + wm + mi * 16 + g;
#pragma unroll
        for (int ni = 0; ni < 8; ++ni) {
            const int cb = n0 + wn + ni * 8 + 2 * q;
            *(float2*)(C + (size_t)r * Ncols + cb) =
                make_float2(acc[mi][ni][0], acc[mi][ni][1]);
            *(float2*)(C + (size_t)(r + 8) * Ncols + cb) =
                make_float2(acc[mi][ni][2], acc[mi][ni][3]);
        }
    }
}

__global__ void __launch_bounds__(256, 2)
gemm1_mma_k() { gemm_f16_body(d_ha, d_hb1, d_proj, PROJC, HIDm); }
__global__ void __launch_bounds__(256, 2)
gemm2_mma_k(float* __restrict__ C) { gemm_f16_body(d_gh, d_hb2, C, HIDm, INTERC); }

// ---------------- fused: depthwise conv+SiLU  ||  dt softplus+cumsum ----------------
// grid (41, Lq): x<40 -> conv block; x==40 && y<1024 -> dt block (h=y&127, c=y>>7)
__global__ void __launch_bounds__(256)
conv_dt_k(const float* __restrict__ w, const float* __restrict__ b,
          const float* __restrict__ dt_bias, const float* __restrict__ A_log) {
    if (blockIdx.x < 40) {
        int c = blockIdx.x * 256 + threadIdx.x;
        int l = blockIdx.y;
        float acc = b[c];
#pragma unroll
        for (int k = 0; k < Kk; ++k) {
            int ls = l - (Kk - 1) + k;
            if (ls >= 0) acc += w[c * Kk + k] * d_proj[(size_t)ls * PROJC + INTERC + c];
        }
        d_xbc[(size_t)l * CONVC + c] = acc / (1.f + __expf(-acc));
    } else {
        if (blockIdx.y >= 1024) return;
        int h = blockIdx.y & 127, c = blockIdx.y >> 7, t = threadIdx.x;
        int l = c * CSz + t;
        float x = d_proj[(size_t)l * PROJC + (INTERC + CONVC) + h] + dt_bias[h];
        float sp = fmaxf(x, 0.f) + log1pf(expf(-fabsf(x)));
        float dtv = fmaxf(sp, 0.f);
        float A = -expf(A_log[h]);
        __shared__ float s[CSz];
        s[t] = dtv * A;
        __syncthreads();
        for (int off = 1; off < CSz; off <<= 1) {
            float v = (t >= off) ? s[t - off] : 0.f;
            __syncthreads();
            s[t] += v;
            __syncthreads();
        }
        d_dt [(size_t)l * Hh + h] = dtv;
        d_cum[(size_t)l * Hh + h] = s[t];
    }
}

// ---------------- fused: intra-chunk  ||  chunk-states ----------------
// grid (5, Hh, NC): x<4 -> intra tile it=x; x==4 -> states for (h,c).
// Both only READ xbc/dt/cum; writes disjoint (d_y vs d_st).
#define IT_SMEM ((2 * 128 * 68 + 2 * 64 * 68 + 192) * 4)
__global__ void __launch_bounds__(256, 2)
ssd_intra_states_k() {
    extern __shared__ float sdyn[];
    const int h = blockIdx.y, c = blockIdx.z;
    const int g = h >> 4;
    const int tid = threadIdx.x;
    const int tx = tid & 15, ty = tid >> 4;

    if (blockIdx.x < 4) {
        // ================= intra branch =================
        float* CsT = sdyn;                 // [n][i]  128x68
        float* BsT = CsT + 128 * 68;       // [n][j]  128x68
        float* SsT = BsT + 128 * 68;       // [j][i]   64x68
        float* Xs  = SsT + 64 * 68;        // [j][p]   64x68
        float* cum_i = Xs + 64 * 68;
        float* cum_j = cum_i + 64;
        float* dtj   = cum_j + 64;

        const int it = blockIdx.x;
        const int li0 = c * CSz + it * 64;
        const int ccol = INTERC + Gg * Nn + g * Nn;
        const int bcol = INTERC + g * Nn;

#pragma unroll
        for (int rep = 0; rep < 2; ++rep) {
            int bb = tid + rep * 256;
            int bi = (bb & 15) * 4;
            int bn = (bb >> 4) * 4;
            float4 r0 = *(const float4*)(&d_xbc[(size_t)(li0 + bi + 0) * CONVC + ccol + bn]);
            float4 r1 = *(const float4*)(&d_xbc[(size_t)(li0 + bi + 1) * CONVC + ccol + bn]);
            float4 r2 = *(const float4*)(&d_xbc[(size_t)(li0 + bi + 2) * CONVC + ccol + bn]);
            float4 r3 = *(const float4*)(&d_xbc[(size_t)(li0 + bi + 3) * CONVC + ccol + bn]);
            *(float4*)&CsT[(bn + 0) * 68 + bi] = make_float4(r0.x, r1.x, r2.x, r3.x);
            *(float4*)&CsT[(bn + 1) * 68 + bi] = make_float4(r0.y, r1.y, r2.y, r3.y);
            *(float4*)&CsT[(bn + 2) * 68 + bi] = make_float4(r0.z, r1.z, r2.z, r3.z);
            *(float4*)&CsT[(bn + 3) * 68 + bi] = make_float4(r0.w, r1.w, r2.w, r3.w);
        }
        if (tid < 64) cum_i[tid] = d_cum[(size_t)(li0 + tid) * Hh + h];

        float yacc[4][4];
#pragma unroll
        for (int i = 0; i < 4; ++i)
#pragma unroll
            for (int j = 0; j < 4; ++j) yacc[i][j] = 0.f;

        for (int jt = 0; jt <= it; ++jt) {
            const int lj0 = c * CSz + jt * 64;
            __syncthreads();
#pragma unroll
            for (int rep = 0; rep < 2; ++rep) {
                int bb = tid + rep * 256;
                int bi = (bb & 15) * 4;
                int bn = (bb >> 4) * 4;
                float4 r0 = *(const float4*)(&d_xbc[(size_t)(lj0 + bi + 0) * CONVC + bcol + bn]);
                float4 r1 = *(const float4*)(&d_xbc[(size_t)(lj0 + bi + 1) * CONVC + bcol + bn]);
                float4 r2 = *(const float4*)(&d_xbc[(size_t)(lj0 + bi + 2) * CONVC + bcol + bn]);
                float4 r3 = *(const float4*)(&d_xbc[(size_t)(lj0 + bi + 3) * CONVC + bcol + bn]);
                *(float4*)&BsT[(bn + 0) * 68 + bi] = make_float4(r0.x, r1.x, r2.x, r3.x);
                *(float4*)&BsT[(bn + 1) * 68 + bi] = make_float4(r0.y, r1.y, r2.y, r3.y);
                *(float4*)&BsT[(bn + 2) * 68 + bi] = make_float4(r0.z, r1.z, r2.z, r3.z);
                *(float4*)&BsT[(bn + 3) * 68 + bi] = make_float4(r0.w, r1.w, r2.w, r3.w);
            }
#pragma unroll
            for (int rep = 0; rep < 4; ++rep) {
                int idx = tid + rep * 256;
                int r = idx >> 4, qq = idx & 15;
                *(float4*)&Xs[r * 68 + qq * 4] =
                    *(const float4*)(&d_xbc[(size_t)(lj0 + r) * CONVC + h * Pp + qq * 4]);
            }
            if (tid < 64) {
                cum_j[tid] = d_cum[(size_t)(lj0 + tid) * Hh + h];
                dtj  [tid] = d_dt [(size_t)(lj0 + tid) * Hh + h];
            }
            __syncthreads();

            float sacc[4][4];
#pragma unroll
            for (int i = 0; i < 4; ++i)
#pragma unroll
                for (int j = 0; j < 4; ++j) sacc[i][j] = 0.f;
#pragma unroll 8
            for (int kk = 0; kk < 128; ++kk) {
                float4 a4 = *(const float4*)&CsT[kk * 68 + ty * 4];
                float4 b4 = *(const float4*)&BsT[kk * 68 + tx * 4];
                float a[4] = {a4.x, a4.y, a4.z, a4.w};
                float b[4] = {b4.x, b4.y, b4.z, b4.w};
#pragma unroll
                for (int i = 0; i < 4; ++i)
#pragma unroll
                    for (int j = 0; j < 4; ++j) sacc[i][j] += a[i] * b[j];
            }
#pragma unroll
            for (int jj = 0; jj < 4; ++jj) {
                int gj = jt * 64 + tx * 4 + jj;
                float cjv = cum_j[tx * 4 + jj];
                float djv = dtj[tx * 4 + jj];
                float v[4];
#pragma unroll
                for (int ii = 0; ii < 4; ++ii) {
                    int gi = it * 64 + ty * 4 + ii;
                    v[ii] = (gi >= gj) ? sacc[ii][jj] * __expf(cum_i[ty * 4 + ii] - cjv) * djv : 0.f;
                }
                *(float4*)&SsT[(tx * 4 + jj) * 68 + ty * 4] = make_float4(v[0], v[1], v[2], v[3]);
            }
            __syncthreads();

#pragma unroll 8
            for (int kkj = 0; kkj < 64; ++kkj) {
                float4 a4 = *(const float4*)&SsT[kkj * 68 + ty * 4];
                float4 b4 = *(const float4*)&Xs[kkj * 68 + tx * 4];
                float a[4] = {a4.x, a4.y, a4.z, a4.w};
                float b[4] = {b4.x, b4.y, b4.z, b4.w};
#pragma unroll
                for (int i = 0; i < 4; ++i)
#pragma unroll
                    for (int j = 0; j < 4; ++j) yacc[i][j] += a[i] * b[j];
            }
        }
#pragma unroll
        for (int i = 0; i < 4; ++i) {
            *(float4*)(&d_y[(size_t)(li0 + ty * 4 + i) * INTERC + h * Pp + tx * 4]) =
                make_float4(yacc[i][0], yacc[i][1], yacc[i][2], yacc[i][3]);
        }
    } else {
        // ================= states branch =================
        float* Xs  = sdyn;                 // [32][68]
        float* Bsh = Xs + 32 * 68;         // [32][132]
        float* ws  = Bsh + 32 * 132;       // [32]

        float acc[4][8];
#pragma unroll
        for (int i = 0; i < 4; ++i)
#pragma unroll
            for (int j = 0; j < 8; ++j) acc[i][j] = 0.f;

        const float cum_last = d_cum[(size_t)(c * CSz + CSz - 1) * Hh + h];

        for (int j0 = 0; j0 < CSz; j0 += 32) {
            __syncthreads();
#pragma unroll
            for (int rep = 0; rep < 2; ++rep) {
                int idx = tid + rep * 256;
                int r = idx >> 4, q = idx & 15;
                *(float4*)&Xs[r * 68 + q * 4] =
                    *(const float4*)(&d_xbc[(size_t)(c * CSz + j0 + r) * CONVC + h * Pp + q * 4]);
            }
#pragma unroll
            for (int rep = 0; rep < 4; ++rep) {
                int idx = tid + rep * 256;
                int r = idx >> 5, q = idx & 31;
                *(float4*)&Bsh[r * 132 + q * 4] =
                    *(const float4*)(&d_xbc[(size_t)(c * CSz + j0 + r) * CONVC + INTERC + g * Nn + q * 4]);
            }
            if (tid < 32) {
                int l = c * CSz + j0 + tid;
                ws[tid] = d_dt[(size_t)l * Hh + h] * __expf(cum_last - d_cum[(size_t)l * Hh + h]);
            }
            __syncthreads();
#pragma unroll 4
            for (int j = 0; j < 32; ++j) {
                float w = ws[j];
                float4 a4 = *(const float4*)&Xs[j * 68 + ty * 4];
                float aw[4] = {a4.x * w, a4.y * w, a4.z * w, a4.w * w};
                float4 b0 = *(const float4*)&Bsh[j * 132 + tx * 8];
                float4 b1 = *(const float4*)&Bsh[j * 132 + tx * 8 + 4];
                float b[8] = {b0.x, b0.y, b0.z, b0.w, b1.x, b1.y, b1.z, b1.w};
#pragma unroll
                for (int i = 0; i < 4; ++i)
#pragma unroll
                    for (int jn = 0; jn < 8; ++jn) acc[i][jn] += aw[i] * b[jn];
            }
        }
#pragma unroll
        for (int i = 0; i < 4; ++i) {
            size_t base = ((size_t)(c * Hh + h) * Pp + ty * 4 + i) * Nn + tx * 8;
            *(float4*)&d_st[base]     = make_float4(acc[i][0], acc[i][1], acc[i][2], acc[i][3]);
            *(float4*)&d_st[base + 4] = make_float4(acc[i][4], acc[i][5], acc[i][6], acc[i][7]);
        }
    }
}

// ---------------- inter-chunk scan ----------------
__global__ void __launch_bounds__(256)
ssd_scan_k() {
    int idx = blockIdx.x * 256 + threadIdx.x;
    if (idx >= Hh * Pp * Nn) return;
    int h = idx / (Pp * Nn);
    float carry = 0.f;
#pragma unroll
    for (int c = 0; c < NC; ++c) {
        d_prev[(size_t)c * Hh * Pp * Nn + idx] = carry;
        float cdec = __expf(d_cum[(size_t)(c * CSz + CSz - 1) * Hh + h]);
        carry = cdec * carry + d_st[(size_t)c * Hh * Pp * Nn + idx];
    }
}

// ---------------- inter-chunk output + D*x ----------------
__global__ void __launch_bounds__(256)
ssd_inter_k(const float* __restrict__ Dp) {
    const int it = blockIdx.x, h = blockIdx.y, c = blockIdx.z;
    const int g = h >> 4;
    const int tid = threadIdx.x;
    const int tx = tid & 15, ty = tid >> 4;

    __shared__ float CsT[64 * 68];
    __shared__ float Pn [64 * 68];

    const int li0 = c * CSz + it * 64;
    const int ccol = INTERC + Gg * Nn + g * Nn;
    const size_t pbase = ((size_t)(c * Hh + h) * Pp) * Nn;

    float acc[4][4];
#pragma unroll
    for (int i = 0; i < 4; ++i)
#pragma unroll
        for (int j = 0; j < 4; ++j) acc[i][j] = 0.f;

#pragma unroll
    for (int nt = 0; nt < 2; ++nt) {
        __syncthreads();
        {
            int bi = (tid & 15) * 4;
            int bn = (tid >> 4) * 4;
            float4 r0 = *(const float4*)(&d_xbc[(size_t)(li0 + bi + 0) * CONVC + ccol + nt * 64 + bn]);
            float4 r1 = *(const float4*)(&d_xbc[(size_t)(li0 + bi + 1) * CONVC + ccol + nt * 64 + bn]);
            float4 r2 = *(const float4*)(&d_xbc[(size_t)(li0 + bi + 2) * CONVC + ccol + nt * 64 + bn]);
            float4 r3 = *(const float4*)(&d_xbc[(size_t)(li0 + bi + 3) * CONVC + ccol + nt * 64 + bn]);
            *(float4*)&CsT[(bn + 0) * 68 + bi] = make_float4(r0.x, r1.x, r2.x, r3.x);
            *(float4*)&CsT[(bn + 1) * 68 + bi] = make_float4(r0.y, r1.y, r2.y, r3.y);
            *(float4*)&CsT[(bn + 2) * 68 + bi] = make_float4(r0.z, r1.z, r2.z, r3.z);
            *(float4*)&CsT[(bn + 3) * 68 + bi] = make_float4(r0.w, r1.w, r2.w, r3.w);
            float4 p0 = *(const float4*)(&d_prev[pbase + (size_t)(bi + 0) * Nn + nt * 64 + bn]);
            float4 p1 = *(const float4*)(&d_prev[pbase + (size_t)(bi + 1) * Nn + nt * 64 + bn]);
            float4 p2 = *(const float4*)(&d_prev[pbase + (size_t)(bi + 2) * Nn + nt * 64 + bn]);
            float4 p3 = *(const float4*)(&d_prev[pbase + (size_t)(bi + 3) * Nn + nt * 64 + bn]);
            *(float4*)&Pn[(bn + 0) * 68 + bi] = make_float4(p0.x, p1.x, p2.x, p3.x);
            *(float4*)&Pn[(bn + 1) * 68 + bi] = make_float4(p0.y, p1.y, p2.y, p3.y);
            *(float4*)&Pn[(bn + 2) * 68 + bi] = make_float4(p0.z, p1.z, p2.z, p3.z);
            *(float4*)&Pn[(bn + 3) * 68 + bi] = make_float4(p0.w, p1.w, p2.w, p3.w);
        }
        __syncthreads();
#pragma unroll 8
        for (int kk = 0; kk < 64; ++kk) {
            float4 a4 = *(const float4*)&CsT[kk * 68 + ty * 4];
            float4 b4 = *(const float4*)&Pn[kk * 68 + tx * 4];
            float a[4] = {a4.x, a4.y, a4.z, a4.w};
            float b[4] = {b4.x, b4.y, b4.z, b4.w};
#pragma unroll
            for (int i = 0; i < 4; ++i)
#pragma unroll
                for (int j = 0; j < 4; ++j) acc[i][j] += a[i] * b[j];
        }
    }
    const float Dh = Dp[h];
#pragma unroll
    for (int i = 0; i < 4; ++i) {
        int l = li0 + ty * 4 + i;
        float esc = __expf(d_cum[(size_t)l * Hh + h]);
        size_t yi = (size_t)l * INTERC + h * Pp + tx * 4;
        size_t xi = (size_t)l * CONVC + h * Pp + tx * 4;
        float4 yv = *(const float4*)&d_y[yi];
        float4 xv = *(const float4*)&d_xbc[xi];
        yv.x += esc * acc[i][0] + Dh * xv.x;
        yv.y += esc * acc[i][1] + Dh * xv.y;
        yv.z += esc * acc[i][2] + Dh * xv.z;
        yv.w += esc * acc[i][3] + Dh * xv.w;
        *(float4*)&d_y[yi] = yv;
    }
}

// ---------------- gated RMS group-norm (writes fp16 d_gh) ----------------
__global__ void __launch_bounds__(256)
gated_norm_k(const float* __restrict__ norm_w) {
    const int l = blockIdx.x, grp = blockIdx.y;
    const int tid = threadIdx.x;
    float v[4];
    float ss = 0.f;
#pragma unroll
    for (int i = 0; i < 4; ++i) {
        int col = grp * GSZ + tid + i * 256;
        float gate = d_proj[(size_t)l * PROJC + col];
        float yv = d_y[(size_t)l * INTERC + col];
        float sg = gate / (1.f + __expf(-gate));
        v[i] = yv * sg;
        ss += v[i] * v[i];
    }
#pragma unroll
    for (int off = 16; off; off >>= 1) ss += __shfl_xor_sync(0xffffffffu, ss, off);
    __shared__ float red[8];
    if ((tid & 31) == 0) red[tid >> 5] = ss;
    __syncthreads();
    float tot = red[0] + red[1] + red[2] + red[3] + red[4] + red[5] + red[6] + red[7];
    float rs = rsqrtf(tot / (float)GSZ + EPSf);
#pragma unroll
    for (int i = 0; i < 4; ++i) {
        int col = grp * GSZ + tid + i * 256;
        d_gh[(size_t)l * INTERC + col] = __float2half_rn(v[i] * rs * norm_w[col]);
    }
}

// ---------------- launch ----------------
extern "C" void kernel_launch(void* const* d_in, const int* in_sizes, int n_in,
                              void* d_out, int out_size) {
    const float* input     = (const float*)d_in[0];
    const float* in_proj_w = (const float*)d_in[1];
    const float* conv_w    = (const float*)d_in[2];
    const float* conv_b    = (const float*)d_in[3];
    const float* dt_bias   = (const float*)d_in[4];
    const float* A_log     = (const float*)d_in[5];
    const float* Dp        = (const float*)d_in[6];
    const float* norm_w    = (const float*)d_in[7];
    const float* out_w     = (const float*)d_in[8];
    float* out = (float*)d_out;

    cudaFuncSetAttribute(gemm1_mma_k, cudaFuncAttributeMaxDynamicSharedMemorySize, GM_SMEM);
    cudaFuncSetAttribute(gemm2_mma_k, cudaFuncAttributeMaxDynamicSharedMemorySize, GM_SMEM);
    cudaFuncSetAttribute(ssd_intra_states_k, cudaFuncAttributeMaxDynamicSharedMemorySize, IT_SMEM);

    __half* ha;  cudaGetSymbolAddress((void**)&ha,  d_ha);
    __half* hb1; cudaGetSymbolAddress((void**)&hb1, d_hb1);
    __half* hb2; cudaGetSymbolAddress((void**)&hb2, d_hb2);

    // 0. fp16 pre-converts
    cvt_f16_k<<<(Lq * HIDm / 4 + 255) / 256, 256>>>((const float4*)input, (uint2*)ha, Lq * HIDm / 4);
    cvt_f16_k<<<(PROJC * HIDm / 4 + 255) / 256, 256>>>((const float4*)in_proj_w, (uint2*)hb1, PROJC * HIDm / 4);
    cvt_f16_k<<<(HIDm * INTERC / 4 + 255) / 256, 256>>>((const float4*)out_w, (uint2*)hb2, HIDm * INTERC / 4);

    // 1. in_proj GEMM (fp16 mma)
    gemm1_mma_k<<<dim3(Lq / BMt, PROJC / BNt), 256, GM_SMEM>>>();
    // 2. fused conv+SiLU || dt softplus+cumsum
    conv_dt_k<<<dim3(41, Lq), 256>>>(conv_w, conv_b, dt_bias, A_log);
    // 3. fused intra-chunk || chunk-states
    ssd_intra_states_k<<<dim3(5, Hh, NC), 256, IT_SMEM>>>();
    // 4. inter-chunk sequential scan -> d_prev
    ssd_scan_k<<<(Hh * Pp * Nn) / 256, 256>>>();
    // 5. inter-chunk contribution + D*x -> d_y (final)
    ssd_inter_k<<<dim3(4, Hh, NC), 256>>>(Dp);
    // 6. gated RMS group-norm -> d_gh (fp16)
    gated_norm_k<<<dim3(Lq, Gg), 256>>>(norm_w);
    // 7. out GEMM (fp16 mma)
    gemm2_mma_k<<<dim3(Lq / BMt, HIDm / BNt), 256, GM_SMEM>>>(out);
}

// round 11
// speedup vs baseline: 1.2150x; 1.1808x over previous
#include <cuda_runtime.h>
#include <cuda_fp16.h>
#include <math.h>
#include <stdint.h>

// ---------------- problem constants ----------------
#define Lq     2048
#define HIDm   4096
#define Hh     128
#define Pp     64
#define Nn     128
#define Gg     8
#define Kk     4
#define CSz    256
#define NC     8            // L / CS
#define INTERC 8192         // H*P
#define CONVC  10240        // INTER + 2*G*N
#define PROJC  18560        // INTER + CONV + H
#define GSZ    1024         // INTER / G
#define EPSf   1e-5f

// ---------------- scratch (static device globals; no allocation) ----------------
__device__ float d_proj[(size_t)Lq * PROJC];
__device__ float d_xbc [(size_t)Lq * CONVC];
__device__ float d_dt  [(size_t)Lq * Hh];
__device__ float d_cum [(size_t)Lq * Hh];
__device__ float d_y   [(size_t)Lq * INTERC];
__device__ float d_st  [(size_t)NC * Hh * Pp * Nn];
__device__ float d_prev[(size_t)NC * Hh * Pp * Nn];
// fp16 operands
__device__ __align__(16) __half d_ha  [(size_t)Lq * HIDm];
__device__ __align__(16) __half d_hb1 [(size_t)PROJC * HIDm];
__device__ __align__(16) __half d_hb2 [(size_t)HIDm * INTERC];
__device__ __align__(16) __half d_gh  [(size_t)Lq * INTERC];
__device__ __align__(16) __half d_xbch[(size_t)Lq * CONVC];     // fp16 mirror of xbc

__device__ __forceinline__ uint32_t smem_u32(const void* p) {
    return (uint32_t)__cvta_generic_to_shared(p);
}
__device__ __forceinline__ void cp16(uint32_t dst, const void* src) {
    asm volatile("cp.async.cg.shared.global [%0], [%1], 16;\n" :: "r"(dst), "l"(src));
}
__device__ __forceinline__ void mma_f16(float* c, const uint32_t* a, const uint32_t* b) {
    asm volatile(
        "mma.sync.aligned.m16n8k16.row.col.f32.f16.f16.f32 "
        "{%0,%1,%2,%3}, {%4,%5,%6,%7}, {%8,%9}, {%0,%1,%2,%3};"
        : "+f"(c[0]), "+f"(c[1]), "+f"(c[2]), "+f"(c[3])
        : "r"(a[0]), "r"(a[1]), "r"(a[2]), "r"(a[3]), "r"(b[0]), "r"(b[1]));
}
__device__ __forceinline__ void ldm_x4(uint32_t* r, uint32_t addr) {
    asm volatile("ldmatrix.sync.aligned.m8n8.x4.shared.b16 {%0,%1,%2,%3}, [%4];"
                 : "=r"(r[0]), "=r"(r[1]), "=r"(r[2]), "=r"(r[3]) : "r"(addr));
}

// ---------------- fp32 -> fp16 pre-convert ----------------
__global__ void __launch_bounds__(256)
cvt_f16_k(const float4* __restrict__ in, uint2* __restrict__ outp, int n4) {
    int i = blockIdx.x * 256 + threadIdx.x;
    if (i >= n4) return;
    float4 v = in[i];
    __half2 lo = __floats2half2_rn(v.x, v.y);
    __half2 hi = __floats2half2_rn(v.z, v.w);
    uint2 o;
    o.x = *(const uint32_t*)&lo;
    o.y = *(const uint32_t*)&hi;
    outp[i] = o;
}

// =====================================================================
//  fp16 mma GEMM (R7 config, frozen): CTA 128x128, BK=64, 256 thr,
//  8 warps (4m x 2n), 3-stage ring, ldmatrix, 2 CTAs/SM.
// =====================================================================
#define BMt 128
#define BNt 128
#define BKh 64
#define PADh 72
#define STAGE_H ((BMt + BNt) * PADh)
#define GM_SMEM (3 * STAGE_H * 2)

__device__ __forceinline__ void gemm_f16_body(const __half* __restrict__ A,
                                              const __half* __restrict__ B,
                                              float* __restrict__ C,
                                              int Ncols, int K) {
    extern __shared__ __half smh[];
    const uint32_t sbase = smem_u32(smh);
    const int tid = threadIdx.x, wid = tid >> 5, lane = tid & 31;
    const int g = lane >> 2, q = lane & 3;
    const int m0 = blockIdx.x * BMt;
    const int n0 = blockIdx.y * BNt;
    const int wm = (wid >> 1) * 32;
    const int wn = (wid & 1) * 64;
    const int nk = K / BKh;

    const int a_row = wm + (lane & 15);
    const int a_kh  = ((lane >> 4) & 1) * 8;
    const uint32_t a_off = (uint32_t)(a_row * PADh + a_kh) * 2;
    const int b_nrow = (lane & 7) + ((lane >> 4) & 1) * 8;
    const int b_kh   = ((lane >> 3) & 1) * 8;
    const uint32_t b_off = (uint32_t)(BMt * PADh + (wn + b_nrow) * PADh + b_kh) * 2;

    float acc[2][8][4];
#pragma unroll
    for (int i = 0; i < 2; ++i)
#pragma unroll
        for (int j = 0; j < 8; ++j)
#pragma unroll
            for (int r = 0; r < 4; ++r) acc[i][j][r] = 0.f;

    auto load_stage = [&](int c) {
        const int s = c % 3;
        const int k0 = c * BKh;
        const uint32_t abase = sbase + s * STAGE_H * 2;
        const uint32_t bbase = abase + BMt * PADh * 2;
#pragma unroll
        for (int i = 0; i < 4; ++i) {
            int t = tid + i * 256;
            int r = t >> 3, qq = t & 7;
            cp16(abase + (uint32_t)(r * PADh + qq * 8) * 2,
                 A + (size_t)(m0 + r) * K + k0 + qq * 8);
        }
#pragma unroll
        for (int i = 0; i < 4; ++i) {
            int t = tid + i * 256;
            int r = t >> 3, qq = t & 7;
            cp16(bbase + (uint32_t)(r * PADh + qq * 8) * 2,
                 B + (size_t)(n0 + r) * K + k0 + qq * 8);
        }
        asm volatile("cp.async.commit_group;");
    };

    load_stage(0);
    load_stage(1);

    for (int c = 0; c < nk; ++c) {
        if (c + 1 < nk) {
            asm volatile("cp.async.wait_group 1;");
        } else {
            asm volatile("cp.async.wait_group 0;");
        }
        __syncthreads();

        if (c + 2 < nk) load_stage(c + 2);

        const uint32_t stg = sbase + (uint32_t)(c % 3) * STAGE_H * 2;
        const uint32_t a_addr = stg + a_off;
        const uint32_t b_addr = stg + b_off;

#pragma unroll
        for (int ks = 0; ks < 4; ++ks) {
            const uint32_t kadd = (uint32_t)ks * 32;
            uint32_t af[2][4];
            ldm_x4(af[0], a_addr + kadd);
            ldm_x4(af[1], a_addr + 16 * PADh * 2 + kadd);
            uint32_t bf[4][4];
#pragma unroll
            for (int nb = 0; nb < 4; ++nb)
                ldm_x4(bf[nb], b_addr + (uint32_t)(nb * 16 * PADh) * 2 + kadd);
#pragma unroll
            for (int mi = 0; mi < 2; ++mi)
#pragma unroll
                for (int ni = 0; ni < 8; ++ni)
                    mma_f16(acc[mi][ni], af[mi], &bf[ni >> 1][(ni & 1) * 2]);
        }
    }

#pragma unroll
    for (int mi = 0; mi < 2; ++mi) {
        const int r = m0 + wm + mi * 16 + g;
#pragma unroll
        for (int ni = 0; ni < 8; ++ni) {
            const int cb = n0 + wn + ni * 8 + 2 * q;
            *(float2*)(C + (size_t)r * Ncols + cb) =
                make_float2(acc[mi][ni][0], acc[mi][ni][1]);
            *(float2*)(C + (size_t)(r + 8) * Ncols + cb) =
                make_float2(acc[mi][ni][2], acc[mi][ni][3]);
        }
    }
}

__global__ void __launch_bounds__(256, 2)
gemm1_mma_k() { gemm_f16_body(d_ha, d_hb1, d_proj, PROJC, HIDm); }
__global__ void __launch_bounds__(256, 2)
gemm2_mma_k(float* __restrict__ C) { gemm_f16_body(d_gh, d_hb2, C, HIDm, INTERC); }

// ---------------- fused: depthwise conv+SiLU (f32 + f16 mirror) || dt+cumsum ----------------
__global__ void __launch_bounds__(256)
conv_dt_k(const float* __restrict__ w, const float* __restrict__ b,
          const float* __restrict__ dt_bias, const float* __restrict__ A_log) {
    if (blockIdx.x < 40) {
        int c = blockIdx.x * 256 + threadIdx.x;
        int l = blockIdx.y;
        float acc = b[c];
#pragma unroll
        for (int k = 0; k < Kk; ++k) {
            int ls = l - (Kk - 1) + k;
            if (ls >= 0) acc += w[c * Kk + k] * d_proj[(size_t)ls * PROJC + INTERC + c];
        }
        float v = acc / (1.f + __expf(-acc));
        d_xbc [(size_t)l * CONVC + c] = v;
        d_xbch[(size_t)l * CONVC + c] = __float2half_rn(v);
    } else {
        if (blockIdx.y >= 1024) return;
        int h = blockIdx.y & 127, c = blockIdx.y >> 7, t = threadIdx.x;
        int l = c * CSz + t;
        float x = d_proj[(size_t)l * PROJC + (INTERC + CONVC) + h] + dt_bias[h];
        float sp = fmaxf(x, 0.f) + log1pf(expf(-fabsf(x)));
        float dtv = fmaxf(sp, 0.f);
        float A = -expf(A_log[h]);
        __shared__ float s[CSz];
        s[t] = dtv * A;
        __syncthreads();
        for (int off = 1; off < CSz; off <<= 1) {
            float v = (t >= off) ? s[t - off] : 0.f;
            __syncthreads();
            s[t] += v;
            __syncthreads();
        }
        d_dt [(size_t)l * Hh + h] = dtv;
        d_cum[(size_t)l * Hh + h] = s[t];
    }
}

// ---------------- fused: intra-chunk (fp16 MMA) || chunk-states (fp32) ----------------
// smem halves: Cs 64x136, Bs 64x136, Ss 64x72, Xs 64x72, XsT 64x72; + 3x64 f32
#define CW 136
#define SW 72
#define IT_HALVES (64 * (2 * CW + 3 * SW))
#define IT_SMEM2  (IT_HALVES * 2 + 3 * 64 * 4)     // 63232 B
__global__ void __launch_bounds__(256, 2)
ssd_intra_states_k() {
    extern __shared__ __align__(16) char sraw[];
    const int h = blockIdx.y, c = blockIdx.z;
    const int g = h >> 4;
    const int tid = threadIdx.x;

    if (blockIdx.x < 4) {
        // ================= intra branch: fp16 tensor-core =================
        __half* Cs  = (__half*)sraw;                 // [i][n] 64x136
        __half* Bs  = Cs + 64 * CW;                  // [j][n] 64x136
        __half* Ss  = Bs + 64 * CW;                  // [i][j] 64x72
        __half* Xs  = Ss + 64 * SW;                  // [j][p] 64x72
        __half* XsT = Xs + 64 * SW;                  // [p][j] 64x72
        float* cum_i = (float*)(XsT + 64 * SW);
        float* cum_j = cum_i + 64;
        float* dtj   = cum_j + 64;

        const int it = blockIdx.x;
        const int li0 = c * CSz + it * 64;
        const int ccol = INTERC + Gg * Nn + g * Nn;
        const int bcol = INTERC + g * Nn;

        const int wid = tid >> 5, lane = tid & 31;
        const int gq = lane >> 2, q = lane & 3;
        const int mw = wid >> 1;                     // 0..3 (m16 tile)
        const int nw = wid & 1;                      // 0..1 (n32 half)

        const uint32_t CsB = smem_u32(Cs), BsB = smem_u32(Bs);
        const uint32_t SsB = smem_u32(Ss), XtB = smem_u32(XsT);
        // ldmatrix offsets (proven patterns from main GEMM)
        const uint32_t aS_off = (uint32_t)((mw * 16 + (lane & 15)) * CW + ((lane >> 4) & 1) * 8) * 2;
        const uint32_t bS_off = (uint32_t)((nw * 32 + (lane & 7) + ((lane >> 4) & 1) * 8) * CW + ((lane >> 3) & 1) * 8) * 2;
        const uint32_t aY_off = (uint32_t)((mw * 16 + (lane & 15)) * SW + ((lane >> 4) & 1) * 8) * 2;
        const uint32_t bY_off = (uint32_t)((nw * 32 + (lane & 7) + ((lane >> 4) & 1) * 8) * SW + ((lane >> 3) & 1) * 8) * 2;

        // stage C tile once: 64 rows x 128 halves
#pragma unroll
        for (int rep = 0; rep < 4; ++rep) {
            int idx = tid + rep * 256;
            int r = idx >> 4, qq = idx & 15;
            *(uint4*)&Cs[r * CW + qq * 8] =
                *(const uint4*)&d_xbch[(size_t)(li0 + r) * CONVC + ccol + qq * 8];
        }
        if (tid < 64) cum_i[tid] = d_cum[(size_t)(li0 + tid) * Hh + h];

        float accY[4][4];
#pragma unroll
        for (int i = 0; i < 4; ++i)
#pragma unroll
            for (int j = 0; j < 4; ++j) accY[i][j] = 0.f;

        const int i0 = mw * 16 + gq;

        for (int jt = 0; jt <= it; ++jt) {
            const int lj0 = c * CSz + jt * 64;
            __syncthreads();
            // stage B tile (64x128) + X tile (64x64) + cum/dt
#pragma unroll
            for (int rep = 0; rep < 4; ++rep) {
                int idx = tid + rep * 256;
                int r = idx >> 4, qq = idx & 15;
                *(uint4*)&Bs[r * CW + qq * 8] =
                    *(const uint4*)&d_xbch[(size_t)(lj0 + r) * CONVC + bcol + qq * 8];
            }
#pragma unroll
            for (int rep = 0; rep < 2; ++rep) {
                int idx = tid + rep * 256;
                int r = idx >> 3, qq = idx & 7;
                *(uint4*)&Xs[r * SW + qq * 8] =
                    *(const uint4*)&d_xbch[(size_t)(lj0 + r) * CONVC + h * Pp + qq * 8];
            }
            if (tid < 64) {
                cum_j[tid] = d_cum[(size_t)(lj0 + tid) * Hh + h];
                dtj  [tid] = d_dt [(size_t)(lj0 + tid) * Hh + h];
            }
            __syncthreads();

            // transpose Xs[j][p] -> XsT[p][j] in 2x2 half blocks
#pragma unroll
            for (int rep = 0; rep < 4; ++rep) {
                int idx = tid + rep * 256;           // 0..1023
                int bb = idx >> 5, aa = idx & 31;    // j-block, p-block
                uint32_t u0 = *(uint32_t*)&Xs[(2 * bb) * SW + 2 * aa];
                uint32_t u1 = *(uint32_t*)&Xs[(2 * bb + 1) * SW + 2 * aa];
                uint32_t lo = (u0 & 0xffffu) | (u1 << 16);
                uint32_t hi = (u0 >> 16) | (u1 & 0xffff0000u);
                *(uint32_t*)&XsT[(2 * aa) * SW + 2 * bb] = lo;
                *(uint32_t*)&XsT[(2 * aa + 1) * SW + 2 * bb] = hi;
            }

            // ---- S = C_i . B_j^T (64x64, K=128) on tensor cores ----
            float accS[4][4];
#pragma unroll
            for (int i = 0; i < 4; ++i)
#pragma unroll
                for (int j = 0; j < 4; ++j) accS[i][j] = 0.f;
#pragma unroll
            for (int ks = 0; ks < 8; ++ks) {
                const uint32_t kadd = (uint32_t)ks * 32;
                uint32_t af[4];
                ldm_x4(af, CsB + aS_off + kadd);
                uint32_t bf[2][4];
                ldm_x4(bf[0], BsB + bS_off + kadd);
                ldm_x4(bf[1], BsB + bS_off + (uint32_t)(16 * CW) * 2 + kadd);
#pragma unroll
                for (int ni = 0; ni < 4; ++ni)
                    mma_f16(accS[ni], af, &bf[ni >> 1][(ni & 1) * 2]);
            }

            // ---- decay * dt * mask -> Ss (fp16) ----
            {
                const float ci0 = cum_i[i0], ci1 = cum_i[i0 + 8];
                const int gi0 = it * 64 + i0, gi1 = gi0 + 8;
#pragma unroll
                for (int ni = 0; ni < 4; ++ni) {
                    int jb = nw * 32 + ni * 8 + 2 * q;
                    float cj0 = cum_j[jb], cj1 = cum_j[jb + 1];
                    float dj0 = dtj[jb],  dj1 = dtj[jb + 1];
                    int gj0 = jt * 64 + jb, gj1 = gj0 + 1;
                    float v00 = (gi0 >= gj0) ? accS[ni][0] * __expf(ci0 - cj0) * dj0 : 0.f;
                    float v01 = (gi0 >= gj1) ? accS[ni][1] * __expf(ci0 - cj1) * dj1 : 0.f;
                    float v10 = (gi1 >= gj0) ? accS[ni][2] * __expf(ci1 - cj0) * dj0 : 0.f;
                    float v11 = (gi1 >= gj1) ? accS[ni][3] * __expf(ci1 - cj1) * dj1 : 0.f;
                    __half2 h0 = __floats2half2_rn(v00, v01);
                    __half2 h1 = __floats2half2_rn(v10, v11);
                    *(__half2*)&Ss[i0 * SW + jb] = h0;
                    *(__half2*)&Ss[(i0 + 8) * SW + jb] = h1;
                }
            }
            __syncthreads();

            // ---- Y += S' @ X (64x64, K=64) on tensor cores ----
#pragma unroll
            for (int ks = 0; ks < 4; ++ks) {
                const uint32_t kadd = (uint32_t)ks * 32;
                uint32_t af[4];
                ldm_x4(af, SsB + aY_off + kadd);
                uint32_t bf[2][4];
                ldm_x4(bf[0], XtB + bY_off + kadd);
                ldm_x4(bf[1], XtB + bY_off + (uint32_t)(16 * SW) * 2 + kadd);
#pragma unroll
                for (int ni = 0; ni < 4; ++ni)
                    mma_f16(accY[ni], af, &bf[ni >> 1][(ni & 1) * 2]);
            }
        }

        // ---- epilogue: write Y ----
#pragma unroll
        for (int ni = 0; ni < 4; ++ni) {
            int p = nw * 32 + ni * 8 + 2 * q;
            *(float2*)&d_y[(size_t)(li0 + i0) * INTERC + h * Pp + p] =
                make_float2(accY[ni][0], accY[ni][1]);
            *(float2*)&d_y[(size_t)(li0 + i0 + 8) * INTERC + h * Pp + p] =
                make_float2(accY[ni][2], accY[ni][3]);
        }
    } else {
        // ================= states branch (fp32, unchanged) =================
        float* Xs  = (float*)sraw;         // [32][68]
        float* Bsh = Xs + 32 * 68;         // [32][132]
        float* ws  = Bsh + 32 * 132;       // [32]
        const int tx = tid & 15, ty = tid >> 4;

        float acc[4][8];
#pragma unroll
        for (int i = 0; i < 4; ++i)
#pragma unroll
            for (int j = 0; j < 8; ++j) acc[i][j] = 0.f;

        const float cum_last = d_cum[(size_t)(c * CSz + CSz - 1) * Hh + h];

        for (int j0 = 0; j0 < CSz; j0 += 32) {
            __syncthreads();
#pragma unroll
            for (int rep = 0; rep < 2; ++rep) {
                int idx = tid + rep * 256;
                int r = idx >> 4, qn = idx & 15;
                *(float4*)&Xs[r * 68 + qn * 4] =
                    *(const float4*)(&d_xbc[(size_t)(c * CSz + j0 + r) * CONVC + h * Pp + qn * 4]);
            }
#pragma unroll
            for (int rep = 0; rep < 4; ++rep) {
                int idx = tid + rep * 256;
                int r = idx >> 5, qn = idx & 31;
                *(float4*)&Bsh[r * 132 + qn * 4] =
                    *(const float4*)(&d_xbc[(size_t)(c * CSz + j0 + r) * CONVC + INTERC + g * Nn + qn * 4]);
            }
            if (tid < 32) {
                int l = c * CSz + j0 + tid;
                ws[tid] = d_dt[(size_t)l * Hh + h] * __expf(cum_last - d_cum[(size_t)l * Hh + h]);
            }
            __syncthreads();
#pragma unroll 4
            for (int j = 0; j < 32; ++j) {
                float w = ws[j];
                float4 a4 = *(const float4*)&Xs[j * 68 + ty * 4];
                float aw[4] = {a4.x * w, a4.y * w, a4.z * w, a4.w * w};
                float4 b0 = *(const float4*)&Bsh[j * 132 + tx * 8];
                float4 b1 = *(const float4*)&Bsh[j * 132 + tx * 8 + 4];
                float b[8] = {b0.x, b0.y, b0.z, b0.w, b1.x, b1.y, b1.z, b1.w};
#pragma unroll
                for (int i = 0; i < 4; ++i)
#pragma unroll
                    for (int jn = 0; jn < 8; ++jn) acc[i][jn] += aw[i] * b[jn];
            }
        }
#pragma unroll
        for (int i = 0; i < 4; ++i) {
            size_t base = ((size_t)(c * Hh + h) * Pp + ty * 4 + i) * Nn + tx * 8;
            *(float4*)&d_st[base]     = make_float4(acc[i][0], acc[i][1], acc[i][2], acc[i][3]);
            *(float4*)&d_st[base + 4] = make_float4(acc[i][4], acc[i][5], acc[i][6], acc[i][7]);
        }
    }
}

// ---------------- inter-chunk scan ----------------
__global__ void __launch_bounds__(256)
ssd_scan_k() {
    int idx = blockIdx.x * 256 + threadIdx.x;
    if (idx >= Hh * Pp * Nn) return;
    int h = idx / (Pp * Nn);
    float carry = 0.f;
#pragma unroll
    for (int c = 0; c < NC; ++c) {
        d_prev[(size_t)c * Hh * Pp * Nn + idx] = carry;
        float cdec = __expf(d_cum[(size_t)(c * CSz + CSz - 1) * Hh + h]);
        carry = cdec * carry + d_st[(size_t)c * Hh * Pp * Nn + idx];
    }
}

// ---------------- inter-chunk output + D*x ----------------
__global__ void __launch_bounds__(256)
ssd_inter_k(const float* __restrict__ Dp) {
    const int it = blockIdx.x, h = blockIdx.y, c = blockIdx.z;
    const int g = h >> 4;
    const int tid = threadIdx.x;
    const int tx = tid & 15, ty = tid >> 4;

    __shared__ float CsT[64 * 68];
    __shared__ float Pn [64 * 68];

    const int li0 = c * CSz + it * 64;
    const int ccol = INTERC + Gg * Nn + g * Nn;
    const size_t pbase = ((size_t)(c * Hh + h) * Pp) * Nn;

    float acc[4][4];
#pragma unroll
    for (int i = 0; i < 4; ++i)
#pragma unroll
        for (int j = 0; j < 4; ++j) acc[i][j] = 0.f;

#pragma unroll
    for (int nt = 0; nt < 2; ++nt) {
        __syncthreads();
        {
            int bi = (tid & 15) * 4;
            int bn = (tid >> 4) * 4;
            float4 r0 = *(const float4*)(&d_xbc[(size_t)(li0 + bi + 0) * CONVC + ccol + nt * 64 + bn]);
            float4 r1 = *(const float4*)(&d_xbc[(size_t)(li0 + bi + 1) * CONVC + ccol + nt * 64 + bn]);
            float4 r2 = *(const float4*)(&d_xbc[(size_t)(li0 + bi + 2) * CONVC + ccol + nt * 64 + bn]);
            float4 r3 = *(const float4*)(&d_xbc[(size_t)(li0 + bi + 3) * CONVC + ccol + nt * 64 + bn]);
            *(float4*)&CsT[(bn + 0) * 68 + bi] = make_float4(r0.x, r1.x, r2.x, r3.x);
            *(float4*)&CsT[(bn + 1) * 68 + bi] = make_float4(r0.y, r1.y, r2.y, r3.y);
            *(float4*)&CsT[(bn + 2) * 68 + bi] = make_float4(r0.z, r1.z, r2.z, r3.z);
            *(float4*)&CsT[(bn + 3) * 68 + bi] = make_float4(r0.w, r1.w, r2.w, r3.w);
            float4 p0 = *(const float4*)(&d_prev[pbase + (size_t)(bi + 0) * Nn + nt * 64 + bn]);
            float4 p1 = *(const float4*)(&d_prev[pbase + (size_t)(bi + 1) * Nn + nt * 64 + bn]);
            float4 p2 = *(const float4*)(&d_prev[pbase + (size_t)(bi + 2) * Nn + nt * 64 + bn]);
            float4 p3 = *(const float4*)(&d_prev[pbase + (size_t)(bi + 3) * Nn + nt * 64 + bn]);
            *(float4*)&Pn[(bn + 0) * 68 + bi] = make_float4(p0.x, p1.x, p2.x, p3.x);
            *(float4*)&Pn[(bn + 1) * 68 + bi] = make_float4(p0.y, p1.y, p2.y, p3.y);
            *(float4*)&Pn[(bn + 2) * 68 + bi] = make_float4(p0.z, p1.z, p2.z, p3.z);
            *(float4*)&Pn[(bn + 3) * 68 + bi] = make_float4(p0.w, p1.w, p2.w, p3.w);
        }
        __syncthreads();
#pragma unroll 8
        for (int kk = 0; kk < 64; ++kk) {
            float4 a4 = *(const float4*)&CsT[kk * 68 + ty * 4];
            float4 b4 = *(const float4*)&Pn[kk * 68 + tx * 4];
            float a[4] = {a4.x, a4.y, a4.z, a4.w};
            float b[4] = {b4.x, b4.y, b4.z, b4.w};
#pragma unroll
            for (int i = 0; i < 4; ++i)
#pragma unroll
                for (int j = 0; j < 4; ++j) acc[i][j] += a[i] * b[j];
        }
    }
    const float Dh = Dp[h];
#pragma unroll
    for (int i = 0; i < 4; ++i) {
        int l = li0 + ty * 4 + i;
        float esc = __expf(d_cum[(size_t)l * Hh + h]);
        size_t yi = (size_t)l * INTERC + h * Pp + tx * 4;
        size_t xi = (size_t)l * CONVC + h * Pp + tx * 4;
        float4 yv = *(const float4*)&d_y[yi];
        float4 xv = *(const float4*)&d_xbc[xi];
        yv.x += esc * acc[i][0] + Dh * xv.x;
        yv.y += esc * acc[i][1] + Dh * xv.y;
        yv.z += esc * acc[i][2] + Dh * xv.z;
        yv.w += esc * acc[i][3] + Dh * xv.w;
        *(float4*)&d_y[yi] = yv;
    }
}

// ---------------- gated RMS group-norm (writes fp16 d_gh) ----------------
__global__ void __launch_bounds__(256)
gated_norm_k(const float* __restrict__ norm_w) {
    const int l = blockIdx.x, grp = blockIdx.y;
    const int tid = threadIdx.x;
    float v[4];
    float ss = 0.f;
#pragma unroll
    for (int i = 0; i < 4; ++i) {
        int col = grp * GSZ + tid + i * 256;
        float gate = d_proj[(size_t)l * PROJC + col];
        float yv = d_y[(size_t)l * INTERC + col];
        float sg = gate / (1.f + __expf(-gate));
        v[i] = yv * sg;
        ss += v[i] * v[i];
    }
#pragma unroll
    for (int off = 16; off; off >>= 1) ss += __shfl_xor_sync(0xffffffffu, ss, off);
    __shared__ float red[8];
    if ((tid & 31) == 0) red[tid >> 5] = ss;
    __syncthreads();
    float tot = red[0] + red[1] + red[2] + red[3] + red[4] + red[5] + red[6] + red[7];
    float rs = rsqrtf(tot / (float)GSZ + EPSf);
#pragma unroll
    for (int i = 0; i < 4; ++i) {
        int col = grp * GSZ + tid + i * 256;
        d_gh[(size_t)l * INTERC + col] = __float2half_rn(v[i] * rs * norm_w[col]);
    }
}

// ---------------- launch ----------------
extern "C" void kernel_launch(void* const* d_in, const int* in_sizes, int n_in,
                              void* d_out, int out_size) {
    const float* input     = (const float*)d_in[0];
    const float* in_proj_w = (const float*)d_in[1];
    const float* conv_w    = (const float*)d_in[2];
    const float* conv_b    = (const float*)d_in[3];
    const float* dt_bias   = (const float*)d_in[4];
    const float* A_log     = (const float*)d_in[5];
    const float* Dp        = (const float*)d_in[6];
    const float* norm_w    = (const float*)d_in[7];
    const float* out_w     = (const float*)d_in[8];
    float* out = (float*)d_out;

    cudaFuncSetAttribute(gemm1_mma_k, cudaFuncAttributeMaxDynamicSharedMemorySize, GM_SMEM);
    cudaFuncSetAttribute(gemm2_mma_k, cudaFuncAttributeMaxDynamicSharedMemorySize, GM_SMEM);
    cudaFuncSetAttribute(ssd_intra_states_k, cudaFuncAttributeMaxDynamicSharedMemorySize, IT_SMEM2);

    __half* ha;  cudaGetSymbolAddress((void**)&ha,  d_ha);
    __half* hb1; cudaGetSymbolAddress((void**)&hb1, d_hb1);
    __half* hb2; cudaGetSymbolAddress((void**)&hb2, d_hb2);

    // 0. fp16 pre-converts
    cvt_f16_k<<<(Lq * HIDm / 4 + 255) / 256, 256>>>((const float4*)input, (uint2*)ha, Lq * HIDm / 4);
    cvt_f16_k<<<(PROJC * HIDm / 4 + 255) / 256, 256>>>((const float4*)in_proj_w, (uint2*)hb1, PROJC * HIDm / 4);
    cvt_f16_k<<<(HIDm * INTERC / 4 + 255) / 256, 256>>>((const float4*)out_w, (uint2*)hb2, HIDm * INTERC / 4);

    // 1. in_proj GEMM (fp16 mma)
    gemm1_mma_k<<<dim3(Lq / BMt, PROJC / BNt), 256, GM_SMEM>>>();
    // 2. fused conv+SiLU (f32+f16) || dt softplus+cumsum
    conv_dt_k<<<dim3(41, Lq), 256>>>(conv_w, conv_b, dt_bias, A_log);
    // 3. fused intra-chunk (fp16 MMA) || chunk-states (fp32)
    ssd_intra_states_k<<<dim3(5, Hh, NC), 256, IT_SMEM2>>>();
    // 4. inter-chunk sequential scan -> d_prev
    ssd_scan_k<<<(Hh * Pp * Nn) / 256, 256>>>();
    // 5. inter-chunk contribution + D*x -> d_y (final)
    ssd_inter_k<<<dim3(4, Hh, NC), 256>>>(Dp);
    // 6. gated RMS group-norm -> d_gh (fp16)
    gated_norm_k<<<dim3(Lq, Gg), 256>>>(norm_w);
    // 7. out GEMM (fp16 mma)
    gemm2_mma_k<<<dim3(Lq / BMt, HIDm / BNt), 256, GM_SMEM>>>(out);
}

// round 12
// speedup vs baseline: 1.2885x; 1.0605x over previous
#include <cuda_runtime.h>
#include <cuda_fp16.h>
#include <math.h>
#include <stdint.h>

// ---------------- problem constants ----------------
#define Lq     2048
#define HIDm   4096
#define Hh     128
#define Pp     64
#define Nn     128
#define Gg     8
#define Kk     4
#define CSz    256
#define NC     8            // L / CS
#define INTERC 8192         // H*P
#define CONVC  10240        // INTER + 2*G*N
#define PROJC  18560        // INTER + CONV + H
#define GSZ    1024         // INTER / G
#define EPSf   1e-5f

// ---------------- scratch (static device globals; no allocation) ----------------
__device__ float d_proj[(size_t)Lq * PROJC];
__device__ float d_xbc [(size_t)Lq * CONVC];
__device__ float d_dt  [(size_t)Lq * Hh];
__device__ float d_cum [(size_t)Lq * Hh];
__device__ float d_y   [(size_t)Lq * INTERC];
__device__ float d_st  [(size_t)NC * Hh * Pp * Nn];
// fp16 operands
__device__ __align__(16) __half d_ha   [(size_t)Lq * HIDm];
__device__ __align__(16) __half d_hb1  [(size_t)PROJC * HIDm];
__device__ __align__(16) __half d_hb2  [(size_t)HIDm * INTERC];
__device__ __align__(16) __half d_gh   [(size_t)Lq * INTERC];
__device__ __align__(16) __half d_xbch [(size_t)Lq * CONVC];
__device__ __align__(16) __half d_prevh[(size_t)NC * Hh * Pp * Nn];

__device__ __forceinline__ uint32_t smem_u32(const void* p) {
    return (uint32_t)__cvta_generic_to_shared(p);
}
__device__ __forceinline__ void cp16(uint32_t dst, const void* src) {
    asm volatile("cp.async.cg.shared.global [%0], [%1], 16;\n" :: "r"(dst), "l"(src));
}
__device__ __forceinline__ void mma_f16(float* c, const uint32_t* a, const uint32_t* b) {
    asm volatile(
        "mma.sync.aligned.m16n8k16.row.col.f32.f16.f16.f32 "
        "{%0,%1,%2,%3}, {%4,%5,%6,%7}, {%8,%9}, {%0,%1,%2,%3};"
        : "+f"(c[0]), "+f"(c[1]), "+f"(c[2]), "+f"(c[3])
        : "r"(a[0]), "r"(a[1]), "r"(a[2]), "r"(a[3]), "r"(b[0]), "r"(b[1]));
}
__device__ __forceinline__ void ldm_x4(uint32_t* r, uint32_t addr) {
    asm volatile("ldmatrix.sync.aligned.m8n8.x4.shared.b16 {%0,%1,%2,%3}, [%4];"
                 : "=r"(r[0]), "=r"(r[1]), "=r"(r[2]), "=r"(r[3]) : "r"(addr));
}

// ---------------- fp32 -> fp16 pre-convert ----------------
__global__ void __launch_bounds__(256)
cvt_f16_k(const float4* __restrict__ in, uint2* __restrict__ outp, int n4) {
    int i = blockIdx.x * 256 + threadIdx.x;
    if (i >= n4) return;
    float4 v = in[i];
    __half2 lo = __floats2half2_rn(v.x, v.y);
    __half2 hi = __floats2half2_rn(v.z, v.w);
    uint2 o;
    o.x = *(const uint32_t*)&lo;
    o.y = *(const uint32_t*)&hi;
    outp[i] = o;
}

// =====================================================================
//  fp16 mma GEMM (R7 config, frozen)
// =====================================================================
#define BMt 128
#define BNt 128
#define BKh 64
#define PADh 72
#define STAGE_H ((BMt + BNt) * PADh)
#define GM_SMEM (3 * STAGE_H * 2)

__device__ __forceinline__ void gemm_f16_body(const __half* __restrict__ A,
                                              const __half* __restrict__ B,
                                              float* __restrict__ C,
                                              int Ncols, int K) {
    extern __shared__ __half smh[];
    const uint32_t sbase = smem_u32(smh);
    const int tid = threadIdx.x, wid = tid >> 5, lane = tid & 31;
    const int g = lane >> 2, q = lane & 3;
    const int m0 = blockIdx.x * BMt;
    const int n0 = blockIdx.y * BNt;
    const int wm = (wid >> 1) * 32;
    const int wn = (wid & 1) * 64;
    const int nk = K / BKh;

    const int a_row = wm + (lane & 15);
    const int a_kh  = ((lane >> 4) & 1) * 8;
    const uint32_t a_off = (uint32_t)(a_row * PADh + a_kh) * 2;
    const int b_nrow = (lane & 7) + ((lane >> 4) & 1) * 8;
    const int b_kh   = ((lane >> 3) & 1) * 8;
    const uint32_t b_off = (uint32_t)(BMt * PADh + (wn + b_nrow) * PADh + b_kh) * 2;

    float acc[2][8][4];
#pragma unroll
    for (int i = 0; i < 2; ++i)
#pragma unroll
        for (int j = 0; j < 8; ++j)
#pragma unroll
            for (int r = 0; r < 4; ++r) acc[i][j][r] = 0.f;

    auto load_stage = [&](int c) {
        const int s = c % 3;
        const int k0 = c * BKh;
        const uint32_t abase = sbase + s * STAGE_H * 2;
        const uint32_t bbase = abase + BMt * PADh * 2;
#pragma unroll
        for (int i = 0; i < 4; ++i) {
            int t = tid + i * 256;
            int r = t >> 3, qq = t & 7;
            cp16(abase + (uint32_t)(r * PADh + qq * 8) * 2,
                 A + (size_t)(m0 + r) * K + k0 + qq * 8);
        }
#pragma unroll
        for (int i = 0; i < 4; ++i) {
            int t = tid + i * 256;
            int r = t >> 3, qq = t & 7;
            cp16(bbase + (uint32_t)(r * PADh + qq * 8) * 2,
                 B + (size_t)(n0 + r) * K + k0 + qq * 8);
        }
        asm volatile("cp.async.commit_group;");
    };

    load_stage(0);
    load_stage(1);

    for (int c = 0; c < nk; ++c) {
        if (c + 1 < nk) {
            asm volatile("cp.async.wait_group 1;");
        } else {
            asm volatile("cp.async.wait_group 0;");
        }
        __syncthreads();

        if (c + 2 < nk) load_stage(c + 2);

        const uint32_t stg = sbase + (uint32_t)(c % 3) * STAGE_H * 2;
        const uint32_t a_addr = stg + a_off;
        const uint32_t b_addr = stg + b_off;

#pragma unroll
        for (int ks = 0; ks < 4; ++ks) {
            const uint32_t kadd = (uint32_t)ks * 32;
            uint32_t af[2][4];
            ldm_x4(af[0], a_addr + kadd);
            ldm_x4(af[1], a_addr + 16 * PADh * 2 + kadd);
            uint32_t bf[4][4];
#pragma unroll
            for (int nb = 0; nb < 4; ++nb)
                ldm_x4(bf[nb], b_addr + (uint32_t)(nb * 16 * PADh) * 2 + kadd);
#pragma unroll
            for (int mi = 0; mi < 2; ++mi)
#pragma unroll
                for (int ni = 0; ni < 8; ++ni)
                    mma_f16(acc[mi][ni], af[mi], &bf[ni >> 1][(ni & 1) * 2]);
        }
    }

#pragma unroll
    for (int mi = 0; mi < 2; ++mi) {
        const int r = m0 + wm + mi * 16 + g;
#pragma unroll
        for (int ni = 0; ni < 8; ++ni) {
            const int cb = n0 + wn + ni * 8 + 2 * q;
            *(float2*)(C + (size_t)r * Ncols + cb) =
                make_float2(acc[mi][ni][0], acc[mi][ni][1]);
            *(float2*)(C + (size_t)(r + 8) * Ncols + cb) =
                make_float2(acc[mi][ni][2], acc[mi][ni][3]);
        }
    }
}

__global__ void __launch_bounds__(256, 2)
gemm1_mma_k() { gemm_f16_body(d_ha, d_hb1, d_proj, PROJC, HIDm); }
__global__ void __launch_bounds__(256, 2)
gemm2_mma_k(float* __restrict__ C) { gemm_f16_body(d_gh, d_hb2, C, HIDm, INTERC); }

// ---------------- fused: depthwise conv+SiLU (f32 + f16 mirror) || dt+cumsum ----------------
__global__ void __launch_bounds__(256)
conv_dt_k(const float* __restrict__ w, const float* __restrict__ b,
          const float* __restrict__ dt_bias, const float* __restrict__ A_log) {
    if (blockIdx.x < 40) {
        int c = blockIdx.x * 256 + threadIdx.x;
        int l = blockIdx.y;
        float acc = b[c];
#pragma unroll
        for (int k = 0; k < Kk; ++k) {
            int ls = l - (Kk - 1) + k;
            if (ls >= 0) acc += w[c * Kk + k] * d_proj[(size_t)ls * PROJC + INTERC + c];
        }
        float v = acc / (1.f + __expf(-acc));
        d_xbc [(size_t)l * CONVC + c] = v;
        d_xbch[(size_t)l * CONVC + c] = __float2half_rn(v);
    } else {
        if (blockIdx.y >= 1024) return;
        int h = blockIdx.y & 127, c = blockIdx.y >> 7, t = threadIdx.x;
        int l = c * CSz + t;
        float x = d_proj[(size_t)l * PROJC + (INTERC + CONVC) + h] + dt_bias[h];
        float sp = fmaxf(x, 0.f) + log1pf(expf(-fabsf(x)));
        float dtv = fmaxf(sp, 0.f);
        float A = -expf(A_log[h]);
        __shared__ float s[CSz];
        s[t] = dtv * A;
        __syncthreads();
        for (int off = 1; off < CSz; off <<= 1) {
            float v = (t >= off) ? s[t - off] : 0.f;
            __syncthreads();
            s[t] += v;
            __syncthreads();
        }
        d_dt [(size_t)l * Hh + h] = dtv;
        d_cum[(size_t)l * Hh + h] = s[t];
    }
}

// ---------------- fused: intra-chunk (fp16 MMA) || chunk-states (fp32) ----------------
#define CW 136
#define SW 72
#define IT_HALVES (64 * (2 * CW + 3 * SW))
#define IT_SMEM2  (IT_HALVES * 2 + 3 * 64 * 4)
__global__ void __launch_bounds__(256, 2)
ssd_intra_states_k() {
    extern __shared__ __align__(16) char sraw[];
    const int h = blockIdx.y, c = blockIdx.z;
    const int g = h >> 4;
    const int tid = threadIdx.x;

    if (blockIdx.x < 4) {
        __half* Cs  = (__half*)sraw;
        __half* Bs  = Cs + 64 * CW;
        __half* Ss  = Bs + 64 * CW;
        __half* Xs  = Ss + 64 * SW;
        __half* XsT = Xs + 64 * SW;
        float* cum_i = (float*)(XsT + 64 * SW);
        float* cum_j = cum_i + 64;
        float* dtj   = cum_j + 64;

        const int it = blockIdx.x;
        const int li0 = c * CSz + it * 64;
        const int ccol = INTERC + Gg * Nn + g * Nn;
        const int bcol = INTERC + g * Nn;

        const int wid = tid >> 5, lane = tid & 31;
        const int gq = lane >> 2, q = lane & 3;
        const int mw = wid >> 1;
        const int nw = wid & 1;

        const uint32_t CsB = smem_u32(Cs), BsB = smem_u32(Bs);
        const uint32_t SsB = smem_u32(Ss), XtB = smem_u32(XsT);
        const uint32_t aS_off = (uint32_t)((mw * 16 + (lane & 15)) * CW + ((lane >> 4) & 1) * 8) * 2;
        const uint32_t bS_off = (uint32_t)((nw * 32 + (lane & 7) + ((lane >> 4) & 1) * 8) * CW + ((lane >> 3) & 1) * 8) * 2;
        const uint32_t aY_off = (uint32_t)((mw * 16 + (lane & 15)) * SW + ((lane >> 4) & 1) * 8) * 2;
        const uint32_t bY_off = (uint32_t)((nw * 32 + (lane & 7) + ((lane >> 4) & 1) * 8) * SW + ((lane >> 3) & 1) * 8) * 2;

#pragma unroll
        for (int rep = 0; rep < 4; ++rep) {
            int idx = tid + rep * 256;
            int r = idx >> 4, qq = idx & 15;
            *(uint4*)&Cs[r * CW + qq * 8] =
                *(const uint4*)&d_xbch[(size_t)(li0 + r) * CONVC + ccol + qq * 8];
        }
        if (tid < 64) cum_i[tid] = d_cum[(size_t)(li0 + tid) * Hh + h];

        float accY[4][4];
#pragma unroll
        for (int i = 0; i < 4; ++i)
#pragma unroll
            for (int j = 0; j < 4; ++j) accY[i][j] = 0.f;

        const int i0 = mw * 16 + gq;

        for (int jt = 0; jt <= it; ++jt) {
            const int lj0 = c * CSz + jt * 64;
            __syncthreads();
#pragma unroll
            for (int rep = 0; rep < 4; ++rep) {
                int idx = tid + rep * 256;
                int r = idx >> 4, qq = idx & 15;
                *(uint4*)&Bs[r * CW + qq * 8] =
                    *(const uint4*)&d_xbch[(size_t)(lj0 + r) * CONVC + bcol + qq * 8];
            }
#pragma unroll
            for (int rep = 0; rep < 2; ++rep) {
                int idx = tid + rep * 256;
                int r = idx >> 3, qq = idx & 7;
                *(uint4*)&Xs[r * SW + qq * 8] =
                    *(const uint4*)&d_xbch[(size_t)(lj0 + r) * CONVC + h * Pp + qq * 8];
            }
            if (tid < 64) {
                cum_j[tid] = d_cum[(size_t)(lj0 + tid) * Hh + h];
                dtj  [tid] = d_dt [(size_t)(lj0 + tid) * Hh + h];
            }
            __syncthreads();

#pragma unroll
            for (int rep = 0; rep < 4; ++rep) {
                int idx = tid + rep * 256;
                int bb = idx >> 5, aa = idx & 31;
                uint32_t u0 = *(uint32_t*)&Xs[(2 * bb) * SW + 2 * aa];
                uint32_t u1 = *(uint32_t*)&Xs[(2 * bb + 1) * SW + 2 * aa];
                uint32_t lo = (u0 & 0xffffu) | (u1 << 16);
                uint32_t hi = (u0 >> 16) | (u1 & 0xffff0000u);
                *(uint32_t*)&XsT[(2 * aa) * SW + 2 * bb] = lo;
                *(uint32_t*)&XsT[(2 * aa + 1) * SW + 2 * bb] = hi;
            }

            float accS[4][4];
#pragma unroll
            for (int i = 0; i < 4; ++i)
#pragma unroll
                for (int j = 0; j < 4; ++j) accS[i][j] = 0.f;
#pragma unroll
            for (int ks = 0; ks < 8; ++ks) {
                const uint32_t kadd = (uint32_t)ks * 32;
                uint32_t af[4];
                ldm_x4(af, CsB + aS_off + kadd);
                uint32_t bf[2][4];
                ldm_x4(bf[0], BsB + bS_off + kadd);
                ldm_x4(bf[1], BsB + bS_off + (uint32_t)(16 * CW) * 2 + kadd);
#pragma unroll
                for (int ni = 0; ni < 4; ++ni)
                    mma_f16(accS[ni], af, &bf[ni >> 1][(ni & 1) * 2]);
            }

            {
                const float ci0 = cum_i[i0], ci1 = cum_i[i0 + 8];
                const int gi0 = it * 64 + i0, gi1 = gi0 + 8;
#pragma unroll
                for (int ni = 0; ni < 4; ++ni) {
                    int jb = nw * 32 + ni * 8 + 2 * q;
                    float cj0 = cum_j[jb], cj1 = cum_j[jb + 1];
                    float dj0 = dtj[jb],  dj1 = dtj[jb + 1];
                    int gj0 = jt * 64 + jb, gj1 = gj0 + 1;
                    float v00 = (gi0 >= gj0) ? accS[ni][0] * __expf(ci0 - cj0) * dj0 : 0.f;
                    float v01 = (gi0 >= gj1) ? accS[ni][1] * __expf(ci0 - cj1) * dj1 : 0.f;
                    float v10 = (gi1 >= gj0) ? accS[ni][2] * __expf(ci1 - cj0) * dj0 : 0.f;
                    float v11 = (gi1 >= gj1) ? accS[ni][3] * __expf(ci1 - cj1) * dj1 : 0.f;
                    __half2 h0 = __floats2half2_rn(v00, v01);
                    __half2 h1 = __floats2half2_rn(v10, v11);
                    *(__half2*)&Ss[i0 * SW + jb] = h0;
                    *(__half2*)&Ss[(i0 + 8) * SW + jb] = h1;
                }
            }
            __syncthreads();

#pragma unroll
            for (int ks = 0; ks < 4; ++ks) {
                const uint32_t kadd = (uint32_t)ks * 32;
                uint32_t af[4];
                ldm_x4(af, SsB + aY_off + kadd);
                uint32_t bf[2][4];
                ldm_x4(bf[0], XtB + bY_off + kadd);
                ldm_x4(bf[1], XtB + bY_off + (uint32_t)(16 * SW) * 2 + kadd);
#pragma unroll
                for (int ni = 0; ni < 4; ++ni)
                    mma_f16(accY[ni], af, &bf[ni >> 1][(ni & 1) * 2]);
            }
        }

#pragma unroll
        for (int ni = 0; ni < 4; ++ni) {
            int p = nw * 32 + ni * 8 + 2 * q;
            *(float2*)&d_y[(size_t)(li0 + i0) * INTERC + h * Pp + p] =
                make_float2(accY[ni][0], accY[ni][1]);
            *(float2*)&d_y[(size_t)(li0 + i0 + 8) * INTERC + h * Pp + p] =
                make_float2(accY[ni][2], accY[ni][3]);
        }
    } else {
        // ================= states branch (fp32, unchanged) =================
        float* Xs  = (float*)sraw;
        float* Bsh = Xs + 32 * 68;
        float* ws  = Bsh + 32 * 132;
        const int tx = tid & 15, ty = tid >> 4;

        float acc[4][8];
#pragma unroll
        for (int i = 0; i < 4; ++i)
#pragma unroll
            for (int j = 0; j < 8; ++j) acc[i][j] = 0.f;

        const float cum_last = d_cum[(size_t)(c * CSz + CSz - 1) * Hh + h];

        for (int j0 = 0; j0 < CSz; j0 += 32) {
            __syncthreads();
#pragma unroll
            for (int rep = 0; rep < 2; ++rep) {
                int idx = tid + rep * 256;
                int r = idx >> 4, qn = idx & 15;
                *(float4*)&Xs[r * 68 + qn * 4] =
                    *(const float4*)(&d_xbc[(size_t)(c * CSz + j0 + r) * CONVC + h * Pp + qn * 4]);
            }
#pragma unroll
            for (int rep = 0; rep < 4; ++rep) {
                int idx = tid + rep * 256;
                int r = idx >> 5, qn = idx & 31;
                *(float4*)&Bsh[r * 132 + qn * 4] =
                    *(const float4*)(&d_xbc[(size_t)(c * CSz + j0 + r) * CONVC + INTERC + g * Nn + qn * 4]);
            }
            if (tid < 32) {
                int l = c * CSz + j0 + tid;
                ws[tid] = d_dt[(size_t)l * Hh + h] * __expf(cum_last - d_cum[(size_t)l * Hh + h]);
            }
            __syncthreads();
#pragma unroll 4
            for (int j = 0; j < 32; ++j) {
                float w = ws[j];
                float4 a4 = *(const float4*)&Xs[j * 68 + ty * 4];
                float aw[4] = {a4.x * w, a4.y * w, a4.z * w, a4.w * w};
                float4 b0 = *(const float4*)&Bsh[j * 132 + tx * 8];
                float4 b1 = *(const float4*)&Bsh[j * 132 + tx * 8 + 4];
                float b[8] = {b0.x, b0.y, b0.z, b0.w, b1.x, b1.y, b1.z, b1.w};
#pragma unroll
                for (int i = 0; i < 4; ++i)
#pragma unroll
                    for (int jn = 0; jn < 8; ++jn) acc[i][jn] += aw[i] * b[jn];
            }
        }
#pragma unroll
        for (int i = 0; i < 4; ++i) {
            size_t base = ((size_t)(c * Hh + h) * Pp + ty * 4 + i) * Nn + tx * 8;
            *(float4*)&d_st[base]     = make_float4(acc[i][0], acc[i][1], acc[i][2], acc[i][3]);
            *(float4*)&d_st[base + 4] = make_float4(acc[i][4], acc[i][5], acc[i][6], acc[i][7]);
        }
    }
}

// ---------------- inter-chunk scan (writes fp16 prev) ----------------
__global__ void __launch_bounds__(256)
ssd_scan_k() {
    int idx = blockIdx.x * 256 + threadIdx.x;
    if (idx >= Hh * Pp * Nn) return;
    int h = idx / (Pp * Nn);
    float carry = 0.f;
#pragma unroll
    for (int c = 0; c < NC; ++c) {
        d_prevh[(size_t)c * Hh * Pp * Nn + idx] = __float2half_rn(carry);
        float cdec = __expf(d_cum[(size_t)(c * CSz + CSz - 1) * Hh + h]);
        carry = cdec * carry + d_st[(size_t)c * Hh * Pp * Nn + idx];
    }
}

// ---------------- inter-chunk output (fp16 MMA) + D*x ----------------
__global__ void __launch_bounds__(256)
ssd_inter_k(const float* __restrict__ Dp) {
    __shared__ __align__(16) __half Cs[64 * CW];
    __shared__ __align__(16) __half Ph[64 * CW];
    __shared__ float cum_i[64];

    const int it = blockIdx.x, h = blockIdx.y, c = blockIdx.z;
    const int g = h >> 4;
    const int tid = threadIdx.x;
    const int wid = tid >> 5, lane = tid & 31;
    const int gq = lane >> 2, q = lane & 3;
    const int mw = wid >> 1;
    const int nw = wid & 1;

    const int li0 = c * CSz + it * 64;
    const int ccol = INTERC + Gg * Nn + g * Nn;
    const size_t pbase = ((size_t)(c * Hh + h) * Pp) * Nn;

    // stage C (64x128) and prev (64 p-rows x 128 n)
#pragma unroll
    for (int rep = 0; rep < 4; ++rep) {
        int idx = tid + rep * 256;
        int r = idx >> 4, qq = idx & 15;
        *(uint4*)&Cs[r * CW + qq * 8] =
            *(const uint4*)&d_xbch[(size_t)(li0 + r) * CONVC + ccol + qq * 8];
        *(uint4*)&Ph[r * CW + qq * 8] =
            *(const uint4*)&d_prevh[pbase + (size_t)r * Nn + qq * 8];
    }
    if (tid < 64) cum_i[tid] = d_cum[(size_t)(li0 + tid) * Hh + h];
    __syncthreads();

    const uint32_t CsB = smem_u32(Cs), PhB = smem_u32(Ph);
    const uint32_t a_off = (uint32_t)((mw * 16 + (lane & 15)) * CW + ((lane >> 4) & 1) * 8) * 2;
    const uint32_t b_off = (uint32_t)((nw * 32 + (lane & 7) + ((lane >> 4) & 1) * 8) * CW + ((lane >> 3) & 1) * 8) * 2;

    float acc[4][4];
#pragma unroll
    for (int i = 0; i < 4; ++i)
#pragma unroll
        for (int j = 0; j < 4; ++j) acc[i][j] = 0.f;

#pragma unroll
    for (int ks = 0; ks < 8; ++ks) {
        const uint32_t kadd = (uint32_t)ks * 32;
        uint32_t af[4];
        ldm_x4(af, CsB + a_off + kadd);
        uint32_t bf[2][4];
        ldm_x4(bf[0], PhB + b_off + kadd);
        ldm_x4(bf[1], PhB + b_off + (uint32_t)(16 * CW) * 2 + kadd);
#pragma unroll
        for (int ni = 0; ni < 4; ++ni)
            mma_f16(acc[ni], af, &bf[ni >> 1][(ni & 1) * 2]);
    }

    const int i0 = mw * 16 + gq;
    const float esc0 = __expf(cum_i[i0]);
    const float esc1 = __expf(cum_i[i0 + 8]);
    const float Dh = Dp[h];
#pragma unroll
    for (int ni = 0; ni < 4; ++ni) {
        int p = nw * 32 + ni * 8 + 2 * q;
        size_t y0 = (size_t)(li0 + i0) * INTERC + h * Pp + p;
        size_t y1 = (size_t)(li0 + i0 + 8) * INTERC + h * Pp + p;
        size_t x0 = (size_t)(li0 + i0) * CONVC + h * Pp + p;
        size_t x1 = (size_t)(li0 + i0 + 8) * CONVC + h * Pp + p;
        float2 yv0 = *(const float2*)&d_y[y0];
        float2 yv1 = *(const float2*)&d_y[y1];
        float2 xv0 = *(const float2*)&d_xbc[x0];
        float2 xv1 = *(const float2*)&d_xbc[x1];
        yv0.x += esc0 * acc[ni][0] + Dh * xv0.x;
        yv0.y += esc0 * acc[ni][1] + Dh * xv0.y;
        yv1.x += esc1 * acc[ni][2] + Dh * xv1.x;
        yv1.y += esc1 * acc[ni][3] + Dh * xv1.y;
        *(float2*)&d_y[y0] = yv0;
        *(float2*)&d_y[y1] = yv1;
    }
}

// ---------------- gated RMS group-norm (writes fp16 d_gh) ----------------
__global__ void __launch_bounds__(256)
gated_norm_k(const float* __restrict__ norm_w) {
    const int l = blockIdx.x, grp = blockIdx.y;
    const int tid = threadIdx.x;
    float v[4];
    float ss = 0.f;
#pragma unroll
    for (int i = 0; i < 4; ++i) {
        int col = grp * GSZ + tid + i * 256;
        float gate = d_proj[(size_t)l * PROJC + col];
        float yv = d_y[(size_t)l * INTERC + col];
        float sg = gate / (1.f + __expf(-gate));
        v[i] = yv * sg;
        ss += v[i] * v[i];
    }
#pragma unroll
    for (int off = 16; off; off >>= 1) ss += __shfl_xor_sync(0xffffffffu, ss, off);
    __shared__ float red[8];
    if ((tid & 31) == 0) red[tid >> 5] = ss;
    __syncthreads();
    float tot = red[0] + red[1] + red[2] + red[3] + red[4] + red[5] + red[6] + red[7];
    float rs = rsqrtf(tot / (float)GSZ + EPSf);
#pragma unroll
    for (int i = 0; i < 4; ++i) {
        int col = grp * GSZ + tid + i * 256;
        d_gh[(size_t)l * INTERC + col] = __float2half_rn(v[i] * rs * norm_w[col]);
    }
}

// ---------------- launch ----------------
extern "C" void kernel_launch(void* const* d_in, const int* in_sizes, int n_in,
                              void* d_out, int out_size) {
    const float* input     = (const float*)d_in[0];
    const float* in_proj_w = (const float*)d_in[1];
    const float* conv_w    = (const float*)d_in[2];
    const float* conv_b    = (const float*)d_in[3];
    const float* dt_bias   = (const float*)d_in[4];
    const float* A_log     = (const float*)d_in[5];
    const float* Dp        = (const float*)d_in[6];
    const float* norm_w    = (const float*)d_in[7];
    const float* out_w     = (const float*)d_in[8];
    float* out = (float*)d_out;

    cudaFuncSetAttribute(gemm1_mma_k, cudaFuncAttributeMaxDynamicSharedMemorySize, GM_SMEM);
    cudaFuncSetAttribute(gemm2_mma_k, cudaFuncAttributeMaxDynamicSharedMemorySize, GM_SMEM);
    cudaFuncSetAttribute(ssd_intra_states_k, cudaFuncAttributeMaxDynamicSharedMemorySize, IT_SMEM2);

    __half* ha;  cudaGetSymbolAddress((void**)&ha,  d_ha);
    __half* hb1; cudaGetSymbolAddress((void**)&hb1, d_hb1);
    __half* hb2; cudaGetSymbolAddress((void**)&hb2, d_hb2);

    // 0. fp16 pre-converts
    cvt_f16_k<<<(Lq * HIDm / 4 + 255) / 256, 256>>>((const float4*)input, (uint2*)ha, Lq * HIDm / 4);
    cvt_f16_k<<<(PROJC * HIDm / 4 + 255) / 256, 256>>>((const float4*)in_proj_w, (uint2*)hb1, PROJC * HIDm / 4);
    cvt_f16_k<<<(HIDm * INTERC / 4 + 255) / 256, 256>>>((const float4*)out_w, (uint2*)hb2, HIDm * INTERC / 4);

    // 1. in_proj GEMM (fp16 mma)
    gemm1_mma_k<<<dim3(Lq / BMt, PROJC / BNt), 256, GM_SMEM>>>();
    // 2. fused conv+SiLU (f32+f16) || dt softplus+cumsum
    conv_dt_k<<<dim3(41, Lq), 256>>>(conv_w, conv_b, dt_bias, A_log);
    // 3. fused intra-chunk (fp16 MMA) || chunk-states (fp32)
    ssd_intra_states_k<<<dim3(5, Hh, NC), 256, IT_SMEM2>>>();
    // 4. inter-chunk sequential scan -> d_prevh (fp16)
    ssd_scan_k<<<(Hh * Pp * Nn) / 256, 256>>>();
    // 5. inter-chunk contribution (fp16 MMA) + D*x -> d_y (final)
    ssd_inter_k<<<dim3(4, Hh, NC), 256>>>(Dp);
    // 6. gated RMS group-norm -> d_gh (fp16)
    gated_norm_k<<<dim3(Lq, Gg), 256>>>(norm_w);
    // 7. out GEMM (fp16 mma)
    gemm2_mma_k<<<dim3(Lq / BMt, HIDm / BNt), 256, GM_SMEM>>>(out);
}